// round 1
// baseline (speedup 1.0000x reference)
#include <cuda_runtime.h>

#define Bn 8
#define Sn 1024
#define En 1024
#define Hn 16
#define Dn 64
#define Mn (Bn*Sn)                      // 8192 rows for projections
#define ATTN_ELEMS ((size_t)Bn*Hn*Sn*Sn)  // 134217728

// Scratch (allocation-free rule: __device__ globals)
__device__ float g_q[Bn*Hn*Sn*Dn];   // (b,h,s,d)
__device__ float g_k[Bn*Hn*Sn*Dn];
__device__ float g_v[Bn*Hn*Sn*Dn];
__device__ float g_ctx[Bn*Sn*En];    // (b,s,e)

// ---------------------------------------------------------------------------
// Fast exp for x <= 0 (softmax after max-subtraction). FFMA-only, avoids the
// MUFU throughput wall (134M expf would cost ~1ms). Taylor deg-6 of 2^f on
// (-1,0], rel err ~1.5e-5.
// ---------------------------------------------------------------------------
__device__ __forceinline__ float fexp_neg(float x) {
    float t = x * 1.4426950408889634f;
    t = fmaxf(t, -126.0f);
    float nf = truncf(t);        // t <= 0 -> f = t - nf in (-1, 0]
    float f = t - nf;
    float p = 1.5403530e-4f;
    p = fmaf(p, f, 1.3333558e-3f);
    p = fmaf(p, f, 9.6181291e-3f);
    p = fmaf(p, f, 5.5504109e-2f);
    p = fmaf(p, f, 2.4022651e-1f);
    p = fmaf(p, f, 6.9314718e-1f);
    p = fmaf(p, f, 1.0f);
    int ni = (int)nf;
    return __int_as_float((ni + 127) << 23) * p;
}

// ---------------------------------------------------------------------------
// Kernel 1: QKV projections. C[m][n] = sum_k X[m][k]*W[n][k] + bias[n],
// scattered to (b,h,s,d). 128x128 block tile, 8x8 per thread, kc=8.
// grid = (E/128=8, M/128=64, 3)
// ---------------------------------------------------------------------------
__global__ void __launch_bounds__(256) proj_kernel(
    const float* __restrict__ xq, const float* __restrict__ xk, const float* __restrict__ xv,
    const float* __restrict__ wq, const float* __restrict__ bq,
    const float* __restrict__ wk, const float* __restrict__ bk,
    const float* __restrict__ wv, const float* __restrict__ bv)
{
    __shared__ float As[8][128];
    __shared__ float Bs[8][128];

    const int z = blockIdx.z;
    const float* X    = (z == 0) ? xq : ((z == 1) ? xk : xv);
    const float* W    = (z == 0) ? wq : ((z == 1) ? wk : wv);
    const float* bias = (z == 0) ? bq : ((z == 1) ? bk : bv);
    float* dst        = (z == 0) ? g_q : ((z == 1) ? g_k : g_v);

    const int tid = threadIdx.x;
    const int tx = tid & 15, ty = tid >> 4;
    const int m0 = blockIdx.y * 128, n0 = blockIdx.x * 128;
    const int lrow = tid >> 1, lk4 = (tid & 1) * 4;

    const float* Ap = X + (size_t)(m0 + lrow) * En + lk4;
    const float* Bp = W + (size_t)(n0 + lrow) * En + lk4;

    float acc[8][8];
    #pragma unroll
    for (int i = 0; i < 8; i++)
        #pragma unroll
        for (int j = 0; j < 8; j++) acc[i][j] = 0.f;

    for (int k0 = 0; k0 < En; k0 += 8) {
        float4 a = *(const float4*)(Ap + k0);
        float4 b = *(const float4*)(Bp + k0);
        __syncthreads();
        As[lk4+0][lrow] = a.x; As[lk4+1][lrow] = a.y; As[lk4+2][lrow] = a.z; As[lk4+3][lrow] = a.w;
        Bs[lk4+0][lrow] = b.x; Bs[lk4+1][lrow] = b.y; Bs[lk4+2][lrow] = b.z; Bs[lk4+3][lrow] = b.w;
        __syncthreads();
        #pragma unroll
        for (int kk = 0; kk < 8; kk++) {
            float4 a0 = *(const float4*)&As[kk][ty*4];
            float4 a1 = *(const float4*)&As[kk][ty*4 + 64];
            float4 b0 = *(const float4*)&Bs[kk][tx*4];
            float4 b1 = *(const float4*)&Bs[kk][tx*4 + 64];
            float av[8] = {a0.x,a0.y,a0.z,a0.w,a1.x,a1.y,a1.z,a1.w};
            float bv8[8] = {b0.x,b0.y,b0.z,b0.w,b1.x,b1.y,b1.z,b1.w};
            #pragma unroll
            for (int i = 0; i < 8; i++)
                #pragma unroll
                for (int j = 0; j < 8; j++)
                    acc[i][j] = fmaf(av[i], bv8[j], acc[i][j]);
        }
    }

    float4 bias0 = *(const float4*)(bias + n0 + tx*4);
    float4 bias1 = *(const float4*)(bias + n0 + tx*4 + 64);
    const int n_a = n0 + tx*4;
    const int h_a = n_a >> 6, d_a = n_a & 63;
    const int n_b = n_a + 64;
    const int h_b = n_b >> 6, d_b = n_b & 63;

    #pragma unroll
    for (int i = 0; i < 8; i++) {
        int m = m0 + ty*4 + (i & 3) + (i >> 2) * 64;
        int bb = m >> 10, s = m & 1023;
        float4 v0 = make_float4(acc[i][0] + bias0.x, acc[i][1] + bias0.y,
                                acc[i][2] + bias0.z, acc[i][3] + bias0.w);
        float4 v1 = make_float4(acc[i][4] + bias1.x, acc[i][5] + bias1.y,
                                acc[i][6] + bias1.z, acc[i][7] + bias1.w);
        *(float4*)&dst[(((size_t)bb*Hn + h_a)*Sn + s)*Dn + d_a] = v0;
        *(float4*)&dst[(((size_t)bb*Hn + h_b)*Sn + s)*Dn + d_b] = v1;
    }
}

// ---------------------------------------------------------------------------
// Kernel 2: scores = Q @ K^T * (1/8) per (b,h). Raw scores -> attn region.
// grid = (S/128=8, S/128=8, B*H=128)
// ---------------------------------------------------------------------------
__global__ void __launch_bounds__(256) scores_kernel(float* __restrict__ attn)
{
    __shared__ float As[8][128];
    __shared__ float Bs[8][128];

    const int bh = blockIdx.z;
    const float* Q  = g_q + (size_t)bh * (Sn*Dn);
    const float* Kk = g_k + (size_t)bh * (Sn*Dn);

    const int tid = threadIdx.x;
    const int tx = tid & 15, ty = tid >> 4;
    const int m0 = blockIdx.y * 128, n0 = blockIdx.x * 128;
    const int lrow = tid >> 1, lk4 = (tid & 1) * 4;

    const float* Ap = Q  + (size_t)(m0 + lrow) * Dn + lk4;
    const float* Bp = Kk + (size_t)(n0 + lrow) * Dn + lk4;

    float acc[8][8];
    #pragma unroll
    for (int i = 0; i < 8; i++)
        #pragma unroll
        for (int j = 0; j < 8; j++) acc[i][j] = 0.f;

    #pragma unroll
    for (int k0 = 0; k0 < Dn; k0 += 8) {
        float4 a = *(const float4*)(Ap + k0);
        float4 b = *(const float4*)(Bp + k0);
        __syncthreads();
        As[lk4+0][lrow] = a.x; As[lk4+1][lrow] = a.y; As[lk4+2][lrow] = a.z; As[lk4+3][lrow] = a.w;
        Bs[lk4+0][lrow] = b.x; Bs[lk4+1][lrow] = b.y; Bs[lk4+2][lrow] = b.z; Bs[lk4+3][lrow] = b.w;
        __syncthreads();
        #pragma unroll
        for (int kk = 0; kk < 8; kk++) {
            float4 a0 = *(const float4*)&As[kk][ty*4];
            float4 a1 = *(const float4*)&As[kk][ty*4 + 64];
            float4 b0 = *(const float4*)&Bs[kk][tx*4];
            float4 b1 = *(const float4*)&Bs[kk][tx*4 + 64];
            float av[8] = {a0.x,a0.y,a0.z,a0.w,a1.x,a1.y,a1.z,a1.w};
            float bv8[8] = {b0.x,b0.y,b0.z,b0.w,b1.x,b1.y,b1.z,b1.w};
            #pragma unroll
            for (int i = 0; i < 8; i++)
                #pragma unroll
                for (int j = 0; j < 8; j++)
                    acc[i][j] = fmaf(av[i], bv8[j], acc[i][j]);
        }
    }

    float* base = attn + (size_t)bh * ((size_t)Sn*Sn);
    const float sc = 0.125f;
    #pragma unroll
    for (int i = 0; i < 8; i++) {
        int m = m0 + ty*4 + (i & 3) + (i >> 2) * 64;
        float4 v0 = make_float4(acc[i][0]*sc, acc[i][1]*sc, acc[i][2]*sc, acc[i][3]*sc);
        float4 v1 = make_float4(acc[i][4]*sc, acc[i][5]*sc, acc[i][6]*sc, acc[i][7]*sc);
        *(float4*)&base[(size_t)m*Sn + n0 + tx*4]      = v0;
        *(float4*)&base[(size_t)m*Sn + n0 + tx*4 + 64] = v1;
    }
}

// ---------------------------------------------------------------------------
// Kernel 3: in-place row softmax over attn (131072 rows of 1024).
// One warp per row, 8 rows per block. grid = 16384 x 256.
// ---------------------------------------------------------------------------
__global__ void __launch_bounds__(256) softmax_kernel(float* __restrict__ attn)
{
    const int warp = threadIdx.x >> 5;
    const int lane = threadIdx.x & 31;
    const size_t row = (size_t)blockIdx.x * 8 + warp;
    float4* p = (float4*)(attn + row * Sn);

    float4 v[8];
    float mx = -1e30f;
    #pragma unroll
    for (int k = 0; k < 8; k++) {
        v[k] = p[lane + 32*k];
        mx = fmaxf(mx, fmaxf(fmaxf(v[k].x, v[k].y), fmaxf(v[k].z, v[k].w)));
    }
    #pragma unroll
    for (int off = 16; off > 0; off >>= 1)
        mx = fmaxf(mx, __shfl_xor_sync(0xffffffffu, mx, off));

    float sum = 0.f;
    #pragma unroll
    for (int k = 0; k < 8; k++) {
        v[k].x = fexp_neg(v[k].x - mx);
        v[k].y = fexp_neg(v[k].y - mx);
        v[k].z = fexp_neg(v[k].z - mx);
        v[k].w = fexp_neg(v[k].w - mx);
        sum += (v[k].x + v[k].y) + (v[k].z + v[k].w);
    }
    #pragma unroll
    for (int off = 16; off > 0; off >>= 1)
        sum += __shfl_xor_sync(0xffffffffu, sum, off);

    float inv = 1.0f / sum;
    #pragma unroll
    for (int k = 0; k < 8; k++) {
        v[k].x *= inv; v[k].y *= inv; v[k].z *= inv; v[k].w *= inv;
        p[lane + 32*k] = v[k];
    }
}

// ---------------------------------------------------------------------------
// Kernel 4: context = P @ V per (b,h) -> g_ctx (b,s,e). NN gemm.
// Block tile 128(M) x 64(N), kc=8, micro 8x4. grid = (S/128=8, B*H=128)
// ---------------------------------------------------------------------------
__global__ void __launch_bounds__(256) av_kernel(const float* __restrict__ attn)
{
    __shared__ float As[8][128];
    __shared__ float Bs[8][64];

    const int bh = blockIdx.y;
    const int m0 = blockIdx.x * 128;
    const float* P = attn + (size_t)bh * ((size_t)Sn*Sn);
    const float* V = g_v + (size_t)bh * (Sn*Dn);

    const int tid = threadIdx.x;
    const int tx = tid & 15, ty = tid >> 4;
    const int lrow = tid >> 1, lk4 = (tid & 1) * 4;
    const int vk = tid >> 5, vn = (tid & 31) * 2;

    float acc[8][4];
    #pragma unroll
    for (int i = 0; i < 8; i++)
        #pragma unroll
        for (int j = 0; j < 4; j++) acc[i][j] = 0.f;

    for (int k0 = 0; k0 < Sn; k0 += 8) {
        float4 a = *(const float4*)(P + (size_t)(m0 + lrow)*Sn + k0 + lk4);
        float2 b = *(const float2*)(V + (size_t)(k0 + vk)*Dn + vn);
        __syncthreads();
        As[lk4+0][lrow] = a.x; As[lk4+1][lrow] = a.y; As[lk4+2][lrow] = a.z; As[lk4+3][lrow] = a.w;
        Bs[vk][vn] = b.x; Bs[vk][vn+1] = b.y;
        __syncthreads();
        #pragma unroll
        for (int kk = 0; kk < 8; kk++) {
            float4 a0 = *(const float4*)&As[kk][ty*4];
            float4 a1 = *(const float4*)&As[kk][ty*4 + 64];
            float4 b0 = *(const float4*)&Bs[kk][tx*4];
            float av[8] = {a0.x,a0.y,a0.z,a0.w,a1.x,a1.y,a1.z,a1.w};
            float bv4[4] = {b0.x,b0.y,b0.z,b0.w};
            #pragma unroll
            for (int i = 0; i < 8; i++)
                #pragma unroll
                for (int j = 0; j < 4; j++)
                    acc[i][j] = fmaf(av[i], bv4[j], acc[i][j]);
        }
    }

    const int bb = bh >> 4, h = bh & 15;
    #pragma unroll
    for (int i = 0; i < 8; i++) {
        int m = m0 + ty*4 + (i & 3) + (i >> 2) * 64;
        float4 v0 = make_float4(acc[i][0], acc[i][1], acc[i][2], acc[i][3]);
        *(float4*)&g_ctx[((size_t)(bb*Sn + m))*En + h*Dn + tx*4] = v0;
    }
}

// ---------------------------------------------------------------------------
// Kernel 5: output = ctx @ out_w^T + out_b. grid = (8, 64)
// ---------------------------------------------------------------------------
__global__ void __launch_bounds__(256) outproj_kernel(
    const float* __restrict__ W, const float* __restrict__ bias, float* __restrict__ Out)
{
    __shared__ float As[8][128];
    __shared__ float Bs[8][128];

    const int tid = threadIdx.x;
    const int tx = tid & 15, ty = tid >> 4;
    const int m0 = blockIdx.y * 128, n0 = blockIdx.x * 128;
    const int lrow = tid >> 1, lk4 = (tid & 1) * 4;

    const float* Ap = g_ctx + (size_t)(m0 + lrow) * En + lk4;
    const float* Bp = W + (size_t)(n0 + lrow) * En + lk4;

    float acc[8][8];
    #pragma unroll
    for (int i = 0; i < 8; i++)
        #pragma unroll
        for (int j = 0; j < 8; j++) acc[i][j] = 0.f;

    for (int k0 = 0; k0 < En; k0 += 8) {
        float4 a = *(const float4*)(Ap + k0);
        float4 b = *(const float4*)(Bp + k0);
        __syncthreads();
        As[lk4+0][lrow] = a.x; As[lk4+1][lrow] = a.y; As[lk4+2][lrow] = a.z; As[lk4+3][lrow] = a.w;
        Bs[lk4+0][lrow] = b.x; Bs[lk4+1][lrow] = b.y; Bs[lk4+2][lrow] = b.z; Bs[lk4+3][lrow] = b.w;
        __syncthreads();
        #pragma unroll
        for (int kk = 0; kk < 8; kk++) {
            float4 a0 = *(const float4*)&As[kk][ty*4];
            float4 a1 = *(const float4*)&As[kk][ty*4 + 64];
            float4 b0 = *(const float4*)&Bs[kk][tx*4];
            float4 b1 = *(const float4*)&Bs[kk][tx*4 + 64];
            float av[8] = {a0.x,a0.y,a0.z,a0.w,a1.x,a1.y,a1.z,a1.w};
            float bv8[8] = {b0.x,b0.y,b0.z,b0.w,b1.x,b1.y,b1.z,b1.w};
            #pragma unroll
            for (int i = 0; i < 8; i++)
                #pragma unroll
                for (int j = 0; j < 8; j++)
                    acc[i][j] = fmaf(av[i], bv8[j], acc[i][j]);
        }
    }

    float4 bias0 = *(const float4*)(bias + n0 + tx*4);
    float4 bias1 = *(const float4*)(bias + n0 + tx*4 + 64);
    #pragma unroll
    for (int i = 0; i < 8; i++) {
        int m = m0 + ty*4 + (i & 3) + (i >> 2) * 64;
        float4 v0 = make_float4(acc[i][0] + bias0.x, acc[i][1] + bias0.y,
                                acc[i][2] + bias0.z, acc[i][3] + bias0.w);
        float4 v1 = make_float4(acc[i][4] + bias1.x, acc[i][5] + bias1.y,
                                acc[i][6] + bias1.z, acc[i][7] + bias1.w);
        *(float4*)&Out[(size_t)m*En + n0 + tx*4]      = v0;
        *(float4*)&Out[(size_t)m*En + n0 + tx*4 + 64] = v1;
    }
}

// ---------------------------------------------------------------------------
extern "C" void kernel_launch(void* const* d_in, const int* in_sizes, int n_in,
                              void* d_out, int out_size)
{
    const float* q_in  = (const float*)d_in[0];
    const float* k_in  = (const float*)d_in[1];
    const float* v_in  = (const float*)d_in[2];
    const float* q_w   = (const float*)d_in[3];
    const float* q_b   = (const float*)d_in[4];
    const float* k_w   = (const float*)d_in[5];
    const float* k_b   = (const float*)d_in[6];
    const float* v_w   = (const float*)d_in[7];
    const float* v_b   = (const float*)d_in[8];
    const float* out_w = (const float*)d_in[9];
    const float* out_b = (const float*)d_in[10];

    float* out  = (float*)d_out;
    float* attn = out;                    // (B,H,S,S)
    float* outp = out + ATTN_ELEMS;       // (B,S,E)

    proj_kernel<<<dim3(8, 64, 3), 256>>>(q_in, k_in, v_in,
                                         q_w, q_b, k_w, k_b, v_w, v_b);
    scores_kernel<<<dim3(8, 8, 128), 256>>>(attn);
    softmax_kernel<<<16384, 256>>>(attn);
    av_kernel<<<dim3(8, 128), 256>>>(attn);
    outproj_kernel<<<dim3(8, 64), 256>>>(out_w, out_b, outp);
}

// round 4
// speedup vs baseline: 1.2461x; 1.2461x over previous
#include <cuda_runtime.h>
#include <cuda_bf16.h>
#include <cstdint>

#define Bn 8
#define Sn 1024
#define En 1024
#define Hn 16
#define Dn 64
#define ATTN_ELEMS ((size_t)Bn*Hn*Sn*Sn)

__device__ float g_q[Bn*Hn*Sn*Dn];     // (b,h,s,d)
__device__ float g_k[Bn*Hn*Sn*Dn];
__device__ float g_v[Bn*Hn*Sn*Dn];
__device__ float g_ctx[Bn*Sn*En];      // (b,s,e)
__device__ float g_psum[Bn*Hn*Sn*8];   // per-(bh,row,nblock) partial exp sums

// ---------------------------------------------------------------------------
// bf16 tensor-core MMA (baseline PTX, works on sm_100 without 'a')
// ---------------------------------------------------------------------------
__device__ __forceinline__ void mma_bf16(float c[4], const uint32_t a[4],
                                         uint32_t b0, uint32_t b1) {
    asm volatile(
        "mma.sync.aligned.m16n8k16.row.col.f32.bf16.bf16.f32 "
        "{%0,%1,%2,%3}, {%4,%5,%6,%7}, {%8,%9}, {%0,%1,%2,%3};"
        : "+f"(c[0]), "+f"(c[1]), "+f"(c[2]), "+f"(c[3])
        : "r"(a[0]), "r"(a[1]), "r"(a[2]), "r"(a[3]), "r"(b0), "r"(b1));
}

// ---------------------------------------------------------------------------
// fp32 -> (hi, lo) bf16 split, stored to K-major smem tiles, row stride 80B.
// Row stride 80B = 20 banks: rows 0..7 start at banks {0,20,8,28,16,4,24,12}
// -> quad fragment loads are bank-conflict-free.
// ---------------------------------------------------------------------------
#define TSTRIDE 80

__device__ __forceinline__ void st_hilo(char* hi, char* lo, int row, int k, float4 v) {
    __nv_bfloat16 h0 = __float2bfloat16(v.x), h1 = __float2bfloat16(v.y);
    __nv_bfloat16 h2 = __float2bfloat16(v.z), h3 = __float2bfloat16(v.w);
    uint32_t hp0 = (uint32_t)__bfloat16_as_ushort(h0) | ((uint32_t)__bfloat16_as_ushort(h1) << 16);
    uint32_t hp1 = (uint32_t)__bfloat16_as_ushort(h2) | ((uint32_t)__bfloat16_as_ushort(h3) << 16);
    __nv_bfloat16 l0 = __float2bfloat16(v.x - __bfloat162float(h0));
    __nv_bfloat16 l1 = __float2bfloat16(v.y - __bfloat162float(h1));
    __nv_bfloat16 l2 = __float2bfloat16(v.z - __bfloat162float(h2));
    __nv_bfloat16 l3 = __float2bfloat16(v.w - __bfloat162float(h3));
    uint32_t lp0 = (uint32_t)__bfloat16_as_ushort(l0) | ((uint32_t)__bfloat16_as_ushort(l1) << 16);
    uint32_t lp1 = (uint32_t)__bfloat16_as_ushort(l2) | ((uint32_t)__bfloat16_as_ushort(l3) << 16);
    char* ph = hi + row * TSTRIDE + k * 2;
    char* pl = lo + row * TSTRIDE + k * 2;
    *(uint32_t*)ph = hp0; *(uint32_t*)(ph + 4) = hp1;
    *(uint32_t*)pl = lp0; *(uint32_t*)(pl + 4) = lp1;
}

// Load a [rows x 32] fp32 chunk (row stride ld) into hi/lo tiles.
__device__ __forceinline__ void load_chunk(const float* __restrict__ src, int ld, int rows,
                                           char* hi, char* lo, int tid) {
    for (int idx = tid; idx < rows * 8; idx += 256) {
        int r = idx >> 3, f = idx & 7;
        float4 v = *(const float4*)(src + (size_t)r * ld + f * 4);
        st_hilo(hi, lo, r, f * 4, v);
    }
}

// ---------------------------------------------------------------------------
// One K=32 chunk of warp-level MMAs with 3-term compensation.
// Warp tile: 32 rows (2 m-tiles) x NT*8 cols.
// ---------------------------------------------------------------------------
template<int NT>
__device__ __forceinline__ void chunk_mma(const char* Ahi, const char* Alo,
                                          const char* Bhi, const char* Blo,
                                          int arow, int bcol, int lane,
                                          float acc[2][NT][4]) {
    const int gid = lane >> 2, tig = lane & 3;
    #pragma unroll
    for (int ks = 0; ks < 2; ks++) {
        const int kq = ks * 16 + tig * 2;
        uint32_t ah[2][4], al[2][4];
        #pragma unroll
        for (int mt = 0; mt < 2; mt++) {
            int r = arow + mt * 16 + gid;
            const char* pa = Ahi + r * TSTRIDE + kq * 2;
            const char* pa8 = pa + 8 * TSTRIDE;
            ah[mt][0] = *(const uint32_t*)pa;       ah[mt][1] = *(const uint32_t*)pa8;
            ah[mt][2] = *(const uint32_t*)(pa+16);  ah[mt][3] = *(const uint32_t*)(pa8+16);
            const char* qa = Alo + r * TSTRIDE + kq * 2;
            const char* qa8 = qa + 8 * TSTRIDE;
            al[mt][0] = *(const uint32_t*)qa;       al[mt][1] = *(const uint32_t*)qa8;
            al[mt][2] = *(const uint32_t*)(qa+16);  al[mt][3] = *(const uint32_t*)(qa8+16);
        }
        #pragma unroll
        for (int nt = 0; nt < NT; nt++) {
            int c = bcol + nt * 8 + gid;
            const char* pb = Bhi + c * TSTRIDE + kq * 2;
            uint32_t bh0 = *(const uint32_t*)pb, bh1 = *(const uint32_t*)(pb + 16);
            const char* qb = Blo + c * TSTRIDE + kq * 2;
            uint32_t bl0 = *(const uint32_t*)qb, bl1 = *(const uint32_t*)(qb + 16);
            #pragma unroll
            for (int mt = 0; mt < 2; mt++) {
                mma_bf16(acc[mt][nt], ah[mt], bh0, bh1);
                mma_bf16(acc[mt][nt], ah[mt], bl0, bl1);
                mma_bf16(acc[mt][nt], al[mt], bh0, bh1);
            }
        }
    }
}

// SMEM offsets (GEMM kernels): Ahi 0, Alo 10240, Bhi 20480, Blo 30720
#define AHI 0
#define ALO 10240
#define BHI 20480
#define BLO 30720
#define RED 40960
#define GEMM_SMEM 40960
#define SCORES_SMEM 41984
// av: Bhi 20480 (64 rows), Blo 25600, inv 30720
#define AV_BHI 20480
#define AV_BLO 25600
#define AV_INV 30720
#define AV_SMEM 31232

// ---------------------------------------------------------------------------
// Kernel 1: QKV projections. Block 128m x 128n, K=1024 (32 chunks).
// grid (8, 64, 3)
// ---------------------------------------------------------------------------
__global__ void __launch_bounds__(256) proj_kernel(
    const float* __restrict__ xq, const float* __restrict__ xk, const float* __restrict__ xv,
    const float* __restrict__ wq, const float* __restrict__ bq,
    const float* __restrict__ wk, const float* __restrict__ bk,
    const float* __restrict__ wv, const float* __restrict__ bv)
{
    extern __shared__ char sm[];
    const int z = blockIdx.z;
    const float* X    = (z == 0) ? xq : ((z == 1) ? xk : xv);
    const float* W    = (z == 0) ? wq : ((z == 1) ? wk : wv);
    const float* bias = (z == 0) ? bq : ((z == 1) ? bk : bv);
    float* dst        = (z == 0) ? g_q : ((z == 1) ? g_k : g_v);

    const int tid = threadIdx.x, lane = tid & 31, wid = tid >> 5;
    const int wm = wid & 3, wn = wid >> 2;
    const int m0 = blockIdx.y * 128, n0 = blockIdx.x * 128;

    float acc[2][8][4];
    #pragma unroll
    for (int i = 0; i < 2; i++)
        #pragma unroll
        for (int j = 0; j < 8; j++)
            #pragma unroll
            for (int l = 0; l < 4; l++) acc[i][j][l] = 0.f;

    for (int c = 0; c < 32; c++) {
        __syncthreads();
        load_chunk(X + (size_t)m0 * En + c * 32, En, 128, sm + AHI, sm + ALO, tid);
        load_chunk(W + (size_t)n0 * En + c * 32, En, 128, sm + BHI, sm + BLO, tid);
        __syncthreads();
        chunk_mma<8>(sm + AHI, sm + ALO, sm + BHI, sm + BLO, wm * 32, wn * 64, lane, acc);
    }

    const int gid = lane >> 2, tig = lane & 3;
    #pragma unroll
    for (int mt = 0; mt < 2; mt++) {
        int m = m0 + wm * 32 + mt * 16 + gid;
        int bb = m >> 10, s = m & 1023;
        #pragma unroll
        for (int nt = 0; nt < 8; nt++) {
            int n = n0 + wn * 64 + nt * 8 + tig * 2;
            int h = n >> 6, d = n & 63;
            float2 bv2 = *(const float2*)(bias + n);
            float* base = dst + (((size_t)bb * Hn + h) * Sn + s) * Dn + d;
            *(float2*)base = make_float2(acc[mt][nt][0] + bv2.x, acc[mt][nt][1] + bv2.y);
            *(float2*)(base + 8 * Dn) = make_float2(acc[mt][nt][2] + bv2.x, acc[mt][nt][3] + bv2.y);
        }
    }
}

// ---------------------------------------------------------------------------
// Kernel 2: scores -> unnormalized exp(QK^T/8) + deterministic partial sums.
// Block 128q x 128k per (b,h); K=64 (2 chunks). grid (8, 8, 128)
// ---------------------------------------------------------------------------
__global__ void __launch_bounds__(256) scores_kernel(float* __restrict__ attn)
{
    extern __shared__ char sm[];
    float* red = (float*)(sm + RED);

    const int tid = threadIdx.x, lane = tid & 31, wid = tid >> 5;
    const int wm = wid & 3, wn = wid >> 2;
    const int bh = blockIdx.z;
    const int m0 = blockIdx.y * 128, n0 = blockIdx.x * 128;

    const float* Q = g_q + (size_t)bh * (Sn * Dn);
    const float* K = g_k + (size_t)bh * (Sn * Dn);

    float acc[2][8][4];
    #pragma unroll
    for (int i = 0; i < 2; i++)
        #pragma unroll
        for (int j = 0; j < 8; j++)
            #pragma unroll
            for (int l = 0; l < 4; l++) acc[i][j][l] = 0.f;

    for (int c = 0; c < 2; c++) {
        __syncthreads();
        load_chunk(Q + (size_t)m0 * Dn + c * 32, Dn, 128, sm + AHI, sm + ALO, tid);
        load_chunk(K + (size_t)n0 * Dn + c * 32, Dn, 128, sm + BHI, sm + BLO, tid);
        __syncthreads();
        chunk_mma<8>(sm + AHI, sm + ALO, sm + BHI, sm + BLO, wm * 32, wn * 64, lane, acc);
    }

    const int gid = lane >> 2, tig = lane & 3;
    float srow[2][2] = {{0.f, 0.f}, {0.f, 0.f}};
    #pragma unroll
    for (int mt = 0; mt < 2; mt++) {
        int m = m0 + wm * 32 + mt * 16 + gid;
        float* arow = attn + ((size_t)bh * Sn + m) * Sn;
        #pragma unroll
        for (int nt = 0; nt < 8; nt++) {
            int n = n0 + wn * 64 + nt * 8 + tig * 2;
            float e0 = __expf(acc[mt][nt][0] * 0.125f);
            float e1 = __expf(acc[mt][nt][1] * 0.125f);
            float e2 = __expf(acc[mt][nt][2] * 0.125f);
            float e3 = __expf(acc[mt][nt][3] * 0.125f);
            srow[mt][0] += e0 + e1;
            srow[mt][1] += e2 + e3;
            *(float2*)(arow + n) = make_float2(e0, e1);
            *(float2*)(arow + 8 * Sn + n) = make_float2(e2, e3);
        }
    }
    // reduce within quads (fixed order -> deterministic)
    #pragma unroll
    for (int mt = 0; mt < 2; mt++)
        #pragma unroll
        for (int hh = 0; hh < 2; hh++) {
            srow[mt][hh] += __shfl_xor_sync(0xffffffffu, srow[mt][hh], 1);
            srow[mt][hh] += __shfl_xor_sync(0xffffffffu, srow[mt][hh], 2);
        }
    if (tig == 0) {
        #pragma unroll
        for (int mt = 0; mt < 2; mt++) {
            red[wn * 128 + wm * 32 + mt * 16 + gid]     = srow[mt][0];
            red[wn * 128 + wm * 32 + mt * 16 + gid + 8] = srow[mt][1];
        }
    }
    __syncthreads();
    if (tid < 128)
        g_psum[(((size_t)bh << 10) + m0 + tid) * 8 + blockIdx.x] = red[tid] + red[128 + tid];
}

// ---------------------------------------------------------------------------
// Kernel 3: normalize attn in-place + context = P @ V.
// Block 128m x 64d per (b,h); K=1024 (32 chunks). grid (8, 128)
// ---------------------------------------------------------------------------
__global__ void __launch_bounds__(256) av_kernel(float* __restrict__ attn)
{
    extern __shared__ char sm[];
    float* inv = (float*)(sm + AV_INV);

    const int tid = threadIdx.x, lane = tid & 31, wid = tid >> 5;
    const int wm = wid & 3, wn = wid >> 2;
    const int bh = blockIdx.y;
    const int m0 = blockIdx.x * 128;

    if (tid < 128) {
        const float* ps = &g_psum[(((size_t)bh << 10) + m0 + tid) * 8];
        float s = ((ps[0] + ps[1]) + (ps[2] + ps[3])) + ((ps[4] + ps[5]) + (ps[6] + ps[7]));
        inv[tid] = 1.0f / s;
    }

    float* Pb = attn + ((size_t)bh * Sn + m0) * Sn;
    const float* Vb = g_v + (size_t)bh * (Sn * Dn);

    float acc[2][4][4];
    #pragma unroll
    for (int i = 0; i < 2; i++)
        #pragma unroll
        for (int j = 0; j < 4; j++)
            #pragma unroll
            for (int l = 0; l < 4; l++) acc[i][j][l] = 0.f;

    for (int c = 0; c < 32; c++) {
        __syncthreads();
        // P chunk: normalize, write back final attn, convert hi/lo
        for (int idx = tid; idx < 128 * 8; idx += 256) {
            int r = idx >> 3, f = idx & 7;
            float* p = Pb + (size_t)r * Sn + c * 32 + f * 4;
            float4 v = *(float4*)p;
            float s = inv[r];
            v.x *= s; v.y *= s; v.z *= s; v.w *= s;
            *(float4*)p = v;
            st_hilo(sm + AHI, sm + ALO, r, f * 4, v);
        }
        // V chunk transposed: Bt[d][k]
        for (int idx = tid; idx < 32 * 16; idx += 256) {
            int k = idx >> 4, f = idx & 15;
            float4 v = *(const float4*)(Vb + (size_t)(c * 32 + k) * Dn + f * 4);
            float xs[4] = {v.x, v.y, v.z, v.w};
            #pragma unroll
            for (int j = 0; j < 4; j++) {
                int d = f * 4 + j;
                __nv_bfloat16 h = __float2bfloat16(xs[j]);
                __nv_bfloat16 l = __float2bfloat16(xs[j] - __bfloat162float(h));
                *(__nv_bfloat16*)(sm + AV_BHI + d * TSTRIDE + k * 2) = h;
                *(__nv_bfloat16*)(sm + AV_BLO + d * TSTRIDE + k * 2) = l;
            }
        }
        __syncthreads();
        chunk_mma<4>(sm + AHI, sm + ALO, sm + AV_BHI, sm + AV_BLO, wm * 32, wn * 32, lane, acc);
    }

    const int gid = lane >> 2, tig = lane & 3;
    const int bb = bh >> 4, h = bh & 15;
    #pragma unroll
    for (int mt = 0; mt < 2; mt++) {
        int m = m0 + wm * 32 + mt * 16 + gid;
        float* base = g_ctx + ((size_t)bb * Sn + m) * En + h * Dn;
        #pragma unroll
        for (int nt = 0; nt < 4; nt++) {
            int d = wn * 32 + nt * 8 + tig * 2;
            *(float2*)(base + d) = make_float2(acc[mt][nt][0], acc[mt][nt][1]);
            *(float2*)(base + 8 * En + d) = make_float2(acc[mt][nt][2], acc[mt][nt][3]);
        }
    }
}

// ---------------------------------------------------------------------------
// Kernel 4: output = ctx @ out_w^T + out_b. grid (8, 64)
// ---------------------------------------------------------------------------
__global__ void __launch_bounds__(256) outproj_kernel(
    const float* __restrict__ W, const float* __restrict__ bias, float* __restrict__ Out)
{
    extern __shared__ char sm[];
    const int tid = threadIdx.x, lane = tid & 31, wid = tid >> 5;
    const int wm = wid & 3, wn = wid >> 2;
    const int m0 = blockIdx.y * 128, n0 = blockIdx.x * 128;

    float acc[2][8][4];
    #pragma unroll
    for (int i = 0; i < 2; i++)
        #pragma unroll
        for (int j = 0; j < 8; j++)
            #pragma unroll
            for (int l = 0; l < 4; l++) acc[i][j][l] = 0.f;

    for (int c = 0; c < 32; c++) {
        __syncthreads();
        load_chunk(g_ctx + (size_t)m0 * En + c * 32, En, 128, sm + AHI, sm + ALO, tid);
        load_chunk(W + (size_t)n0 * En + c * 32, En, 128, sm + BHI, sm + BLO, tid);
        __syncthreads();
        chunk_mma<8>(sm + AHI, sm + ALO, sm + BHI, sm + BLO, wm * 32, wn * 64, lane, acc);
    }

    const int gid = lane >> 2, tig = lane & 3;
    #pragma unroll
    for (int mt = 0; mt < 2; mt++) {
        int m = m0 + wm * 32 + mt * 16 + gid;
        float* orow = Out + (size_t)m * En;
        #pragma unroll
        for (int nt = 0; nt < 8; nt++) {
            int n = n0 + wn * 64 + nt * 8 + tig * 2;
            float2 bv2 = *(const float2*)(bias + n);
            *(float2*)(orow + n) = make_float2(acc[mt][nt][0] + bv2.x, acc[mt][nt][1] + bv2.y);
            *(float2*)(orow + 8 * En + n) = make_float2(acc[mt][nt][2] + bv2.x, acc[mt][nt][3] + bv2.y);
        }
    }
}

// ---------------------------------------------------------------------------
extern "C" void kernel_launch(void* const* d_in, const int* in_sizes, int n_in,
                              void* d_out, int out_size)
{
    const float* q_in  = (const float*)d_in[0];
    const float* k_in  = (const float*)d_in[1];
    const float* v_in  = (const float*)d_in[2];
    const float* q_w   = (const float*)d_in[3];
    const float* q_b   = (const float*)d_in[4];
    const float* k_w   = (const float*)d_in[5];
    const float* k_b   = (const float*)d_in[6];
    const float* v_w   = (const float*)d_in[7];
    const float* v_b   = (const float*)d_in[8];
    const float* out_w = (const float*)d_in[9];
    const float* out_b = (const float*)d_in[10];

    float* out  = (float*)d_out;
    float* attn = out;                  // (B,H,S,S)
    float* outp = out + ATTN_ELEMS;     // (B,S,E)

    proj_kernel<<<dim3(8, 64, 3), 256, GEMM_SMEM>>>(q_in, k_in, v_in,
                                                    q_w, q_b, k_w, k_b, v_w, v_b);
    scores_kernel<<<dim3(8, 8, 128), 256, SCORES_SMEM>>>(attn);
    av_kernel<<<dim3(8, 128), 256, AV_SMEM>>>(attn);
    outproj_kernel<<<dim3(8, 64), 256, GEMM_SMEM>>>(out_w, out_b, outp);
}

// round 6
// speedup vs baseline: 2.2737x; 1.8247x over previous
#include <cuda_runtime.h>
#include <cuda_bf16.h>
#include <cstdint>

#define Bn 8
#define Sn 1024
#define En 1024
#define Hn 16
#define Dn 64
#define ATTN_ELEMS ((size_t)Bn*Hn*Sn*Sn)
#define IN_ELEMS (Bn*Sn*En)     // 8388608
#define W_ELEMS  (En*En)        // 1048576

// Pre-split bf16 operand storage (allocation-free rule: __device__ globals)
__device__ __nv_bfloat16 g_xhi[3*IN_ELEMS], g_xlo[3*IN_ELEMS];   // inputs q,k,v
__device__ __nv_bfloat16 g_whi[4*W_ELEMS],  g_wlo[4*W_ELEMS];    // weights q,k,v,out
__device__ __nv_bfloat16 g_qhi[IN_ELEMS],  g_qlo[IN_ELEMS];      // (b,h,s,d)
__device__ __nv_bfloat16 g_khi[IN_ELEMS],  g_klo[IN_ELEMS];      // (b,h,s,d)
__device__ __nv_bfloat16 g_vthi[IN_ELEMS], g_vtlo[IN_ELEMS];     // (b,h,d,s) transposed
__device__ __nv_bfloat16 g_chi[IN_ELEMS],  g_clo[IN_ELEMS];      // ctx (b,s,e)
__device__ float g_psum[Bn*Hn*Sn*8];
__device__ const float* g_bias_ptr[4];

// ---------------- PTX primitives ----------------
__device__ __forceinline__ uint32_t smem_u32(const void* p) {
    uint32_t a;
    asm("{ .reg .u64 t; cvta.to.shared.u64 t, %1; cvt.u32.u64 %0, t; }" : "=r"(a) : "l"(p));
    return a;
}
__device__ __forceinline__ void cpa16(uint32_t sdst, const void* gsrc) {
    asm volatile("cp.async.cg.shared.global [%0], [%1], 16;" :: "r"(sdst), "l"(gsrc));
}
#define CP_COMMIT() asm volatile("cp.async.commit_group;" ::: "memory")
#define CP_WAIT(N)  asm volatile("cp.async.wait_group %0;" :: "n"(N) : "memory")

#define LDSM4(R, A) asm volatile("ldmatrix.sync.aligned.m8n8.x4.shared.b16 {%0,%1,%2,%3}, [%4];" \
    : "=r"((R)[0]), "=r"((R)[1]), "=r"((R)[2]), "=r"((R)[3]) : "r"(A))

__device__ __forceinline__ void mma_bf16(float c[4], const uint32_t a[4],
                                         uint32_t b0, uint32_t b1) {
    asm volatile(
        "mma.sync.aligned.m16n8k16.row.col.f32.bf16.bf16.f32 "
        "{%0,%1,%2,%3}, {%4,%5,%6,%7}, {%8,%9}, {%0,%1,%2,%3};"
        : "+f"(c[0]), "+f"(c[1]), "+f"(c[2]), "+f"(c[3])
        : "r"(a[0]), "r"(a[1]), "r"(a[2]), "r"(a[3]), "r"(b0), "r"(b1));
}

// ---------------- fp32 -> (hi,lo) bf16 ----------------
__device__ __forceinline__ void split2_u32(float a, float b, uint32_t& hi, uint32_t& lo) {
    __nv_bfloat16 ha = __float2bfloat16(a), hb = __float2bfloat16(b);
    hi = (uint32_t)__bfloat16_as_ushort(ha) | ((uint32_t)__bfloat16_as_ushort(hb) << 16);
    __nv_bfloat16 la = __float2bfloat16(a - __bfloat162float(ha));
    __nv_bfloat16 lb = __float2bfloat16(b - __bfloat162float(hb));
    lo = (uint32_t)__bfloat16_as_ushort(la) | ((uint32_t)__bfloat16_as_ushort(lb) << 16);
}
#define TSTRIDE 80
__device__ __forceinline__ void st_hilo(char* hi, char* lo, int row, int k, float4 v) {
    uint32_t h0, l0, h1, l1;
    split2_u32(v.x, v.y, h0, l0);
    split2_u32(v.z, v.w, h1, l1);
    char* ph = hi + row * TSTRIDE + k * 2;
    char* pl = lo + row * TSTRIDE + k * 2;
    *(uint32_t*)ph = h0; *(uint32_t*)(ph + 4) = h1;
    *(uint32_t*)pl = l0; *(uint32_t*)(pl + 4) = l1;
}

// ---------------------------------------------------------------------------
// Warp MMA on a K=32 chunk, ldmatrix fragments, 3-term compensation.
// ---------------------------------------------------------------------------
template<int NT, int ST>
__device__ __forceinline__ void chunk_mma(uint32_t Ahi, uint32_t Alo,
                                          uint32_t Bhi, uint32_t Blo,
                                          int arow, int bcol, int lane,
                                          float acc[2][NT][4]) {
    const uint32_t aoff = (uint32_t)((arow + (lane & 15)) * ST + (lane >> 4) * 16);
    const int hb = (lane >> 3) & 3;
    const uint32_t boff = (uint32_t)((bcol + (hb >> 1) * 8 + (lane & 7)) * ST + (hb & 1) * 16);
    #pragma unroll
    for (int ks = 0; ks < 2; ks++) {
        uint32_t ah0[4], ah1[4], al0[4], al1[4];
        LDSM4(ah0, Ahi + aoff + ks * 32);
        LDSM4(ah1, Ahi + aoff + 16 * ST + ks * 32);
        LDSM4(al0, Alo + aoff + ks * 32);
        LDSM4(al1, Alo + aoff + 16 * ST + ks * 32);
        #pragma unroll
        for (int np = 0; np < NT / 2; np++) {
            uint32_t bh[4], bl[4];
            LDSM4(bh, Bhi + boff + np * 16 * ST + ks * 32);
            LDSM4(bl, Blo + boff + np * 16 * ST + ks * 32);
            mma_bf16(acc[0][2*np],   ah0, bh[0], bh[1]);
            mma_bf16(acc[0][2*np],   ah0, bl[0], bl[1]);
            mma_bf16(acc[0][2*np],   al0, bh[0], bh[1]);
            mma_bf16(acc[1][2*np],   ah1, bh[0], bh[1]);
            mma_bf16(acc[1][2*np],   ah1, bl[0], bl[1]);
            mma_bf16(acc[1][2*np],   al1, bh[0], bh[1]);
            mma_bf16(acc[0][2*np+1], ah0, bh[2], bh[3]);
            mma_bf16(acc[0][2*np+1], ah0, bl[2], bl[3]);
            mma_bf16(acc[0][2*np+1], al0, bh[2], bh[3]);
            mma_bf16(acc[1][2*np+1], ah1, bh[2], bh[3]);
            mma_bf16(acc[1][2*np+1], ah1, bl[2], bl[3]);
            mma_bf16(acc[1][2*np+1], al1, bh[2], bh[3]);
        }
    }
}

// ---------------------------------------------------------------------------
// Kernel helpers
// ---------------------------------------------------------------------------
__global__ void set_bias_kernel(const float* qb, const float* kb,
                                const float* vb, const float* ob) {
    g_bias_ptr[0] = qb; g_bias_ptr[1] = kb; g_bias_ptr[2] = vb; g_bias_ptr[3] = ob;
}

__global__ void __launch_bounds__(256) split_kernel(
    const float* __restrict__ xq, const float* __restrict__ xk, const float* __restrict__ xv,
    const float* __restrict__ wq, const float* __restrict__ wk,
    const float* __restrict__ wv, const float* __restrict__ wo)
{
    const int z = blockIdx.y;
    const float* src;
    __nv_bfloat16 *dhi, *dlo;
    int n4;
    if (z < 3) {
        src = (z == 0) ? xq : ((z == 1) ? xk : xv);
        dhi = g_xhi + (size_t)z * IN_ELEMS;
        dlo = g_xlo + (size_t)z * IN_ELEMS;
        n4 = IN_ELEMS / 4;
    } else {
        src = (z == 3) ? wq : ((z == 4) ? wk : ((z == 5) ? wv : wo));
        dhi = g_whi + (size_t)(z - 3) * W_ELEMS;
        dlo = g_wlo + (size_t)(z - 3) * W_ELEMS;
        n4 = W_ELEMS / 4;
    }
    int i = blockIdx.x * 256 + threadIdx.x;
    if (i >= n4) return;
    float4 v = ((const float4*)src)[i];
    uint2 hi, lo;
    split2_u32(v.x, v.y, hi.x, lo.x);
    split2_u32(v.z, v.w, hi.y, lo.y);
    ((uint2*)dhi)[i] = hi;
    ((uint2*)dlo)[i] = lo;
}

// ---------------------------------------------------------------------------
// 128x128 bf16 GEMM skeleton with cp.async 2-stage pipeline (K=1024).
// ---------------------------------------------------------------------------
#define PSTG 40960
#define GEMM_SMEM (2*PSTG)

__device__ __forceinline__ void gemm_issue(uint32_t sbase,
    const __nv_bfloat16* Ah, const __nv_bfloat16* Al,
    const __nv_bfloat16* Bh, const __nv_bfloat16* Bl, int tid)
{
    #pragma unroll 2
    for (int idx = tid; idx < 512; idx += 256) {
        int r = idx >> 2, f = idx & 3;
        uint32_t so = (uint32_t)(r * TSTRIDE + f * 16);
        size_t go = (size_t)r * 1024 + f * 8;
        cpa16(sbase + so,         Ah + go);
        cpa16(sbase + 10240 + so, Al + go);
        cpa16(sbase + 20480 + so, Bh + go);
        cpa16(sbase + 30720 + so, Bl + go);
    }
}

template<typename EPI>
__device__ __forceinline__ void gemm_128x128(
    const __nv_bfloat16* Ah, const __nv_bfloat16* Al,
    const __nv_bfloat16* Bh, const __nv_bfloat16* Bl,
    int tid, EPI epi)
{
    extern __shared__ char sm[];
    const uint32_t sb = smem_u32(sm);
    const int lane = tid & 31, wid = tid >> 5;
    const int wm = wid & 3, wn = wid >> 2;

    float acc[2][8][4];
    #pragma unroll
    for (int i = 0; i < 2; i++)
        #pragma unroll
        for (int j = 0; j < 8; j++)
            #pragma unroll
            for (int l = 0; l < 4; l++) acc[i][j][l] = 0.f;

    gemm_issue(sb, Ah, Al, Bh, Bl, tid);
    CP_COMMIT();
    for (int c = 0; c < 32; c++) {
        if (c + 1 < 32) {
            gemm_issue(sb + ((c + 1) & 1) * PSTG,
                       Ah + (c + 1) * 32, Al + (c + 1) * 32,
                       Bh + (c + 1) * 32, Bl + (c + 1) * 32, tid);
            CP_COMMIT();
            CP_WAIT(1);
        } else {
            CP_WAIT(0);
        }
        __syncthreads();
        uint32_t s = sb + (c & 1) * PSTG;
        chunk_mma<8, TSTRIDE>(s, s + 10240, s + 20480, s + 30720,
                              wm * 32, wn * 64, lane, acc);
        __syncthreads();
    }
    epi(acc, wm, wn, lane);
}

// ---------------------------------------------------------------------------
// Kernel 1: QKV projections. grid (8, 64, 3)
// ---------------------------------------------------------------------------
__global__ void __launch_bounds__(256, 2) proj_kernel()
{
    const int z = blockIdx.z;
    const int tid = threadIdx.x;
    const int m0 = blockIdx.y * 128, n0 = blockIdx.x * 128;
    const __nv_bfloat16* Ah = g_xhi + (size_t)z * IN_ELEMS + (size_t)m0 * 1024;
    const __nv_bfloat16* Al = g_xlo + (size_t)z * IN_ELEMS + (size_t)m0 * 1024;
    const __nv_bfloat16* Bh = g_whi + (size_t)z * W_ELEMS + (size_t)n0 * 1024;
    const __nv_bfloat16* Bl = g_wlo + (size_t)z * W_ELEMS + (size_t)n0 * 1024;

    gemm_128x128(Ah, Al, Bh, Bl, tid,
        [&](float acc[2][8][4], int wm, int wn, int lane) {
            const int gid = lane >> 2, tig = lane & 3;
            const float* bias = g_bias_ptr[z];
            #pragma unroll
            for (int mt = 0; mt < 2; mt++) {
                int m = m0 + wm * 32 + mt * 16 + gid;
                int bb = m >> 10, s = m & 1023;
                #pragma unroll
                for (int nt = 0; nt < 8; nt++) {
                    int n = n0 + wn * 64 + nt * 8 + tig * 2;
                    int h = n >> 6, d = n & 63;
                    float2 bv = *(const float2*)(bias + n);
                    float c0 = acc[mt][nt][0] + bv.x, c1 = acc[mt][nt][1] + bv.y;
                    float c2 = acc[mt][nt][2] + bv.x, c3 = acc[mt][nt][3] + bv.y;
                    if (z < 2) {
                        __nv_bfloat16* dh = (z == 0) ? g_qhi : g_khi;
                        __nv_bfloat16* dl = (z == 0) ? g_qlo : g_klo;
                        size_t a0 = (((size_t)bb * Hn + h) * Sn + s) * Dn + d;
                        uint32_t hi, lo;
                        split2_u32(c0, c1, hi, lo);
                        *(uint32_t*)(dh + a0) = hi; *(uint32_t*)(dl + a0) = lo;
                        split2_u32(c2, c3, hi, lo);
                        *(uint32_t*)(dh + a0 + 8 * Dn) = hi;
                        *(uint32_t*)(dl + a0 + 8 * Dn) = lo;
                    } else {
                        size_t a0 = (((size_t)bb * Hn + h) * Dn + d) * Sn + s;
                        __nv_bfloat16 h0 = __float2bfloat16(c0);
                        __nv_bfloat16 h1 = __float2bfloat16(c1);
                        __nv_bfloat16 h2 = __float2bfloat16(c2);
                        __nv_bfloat16 h3 = __float2bfloat16(c3);
                        g_vthi[a0] = h0;        g_vthi[a0 + Sn] = h1;
                        g_vthi[a0 + 8] = h2;    g_vthi[a0 + Sn + 8] = h3;
                        g_vtlo[a0] = __float2bfloat16(c0 - __bfloat162float(h0));
                        g_vtlo[a0 + Sn] = __float2bfloat16(c1 - __bfloat162float(h1));
                        g_vtlo[a0 + 8] = __float2bfloat16(c2 - __bfloat162float(h2));
                        g_vtlo[a0 + Sn + 8] = __float2bfloat16(c3 - __bfloat162float(h3));
                    }
                }
            }
        });
}

// ---------------------------------------------------------------------------
// Kernel 2: scores -> unnormalized exp + partial sums. grid (8, 8, 128)
// smem: Ahi 0  Alo 18432  Bhi 36864  Blo 55296  red 73728 (1024B) -> 74752
// ---------------------------------------------------------------------------
#define SST 144
#define SCORES_SMEM 74752

__global__ void __launch_bounds__(256, 2) scores_kernel(float* __restrict__ attn)
{
    extern __shared__ char sm[];
    const uint32_t sb = smem_u32(sm);
    float* red = (float*)(sm + 73728);   // 256 floats = 1024 B

    const int tid = threadIdx.x, lane = tid & 31, wid = tid >> 5;
    const int wm = wid & 3, wn = wid >> 2;
    const int bh = blockIdx.z;
    const int m0 = blockIdx.y * 128, n0 = blockIdx.x * 128;

    const __nv_bfloat16* Ah = g_qhi + ((size_t)bh * Sn + m0) * Dn;
    const __nv_bfloat16* Al = g_qlo + ((size_t)bh * Sn + m0) * Dn;
    const __nv_bfloat16* Bh = g_khi + ((size_t)bh * Sn + n0) * Dn;
    const __nv_bfloat16* Bl = g_klo + ((size_t)bh * Sn + n0) * Dn;

    #pragma unroll 4
    for (int idx = tid; idx < 1024; idx += 256) {
        int r = idx >> 3, f = idx & 7;
        uint32_t so = (uint32_t)(r * SST + f * 16);
        size_t go = (size_t)r * Dn + f * 8;
        cpa16(sb + so,         Ah + go);
        cpa16(sb + 18432 + so, Al + go);
        cpa16(sb + 36864 + so, Bh + go);
        cpa16(sb + 55296 + so, Bl + go);
    }
    CP_COMMIT();

    float acc[2][8][4];
    #pragma unroll
    for (int i = 0; i < 2; i++)
        #pragma unroll
        for (int j = 0; j < 8; j++)
            #pragma unroll
            for (int l = 0; l < 4; l++) acc[i][j][l] = 0.f;

    CP_WAIT(0);
    __syncthreads();
    chunk_mma<8, SST>(sb, sb + 18432, sb + 36864, sb + 55296,
                      wm * 32, wn * 64, lane, acc);
    chunk_mma<8, SST>(sb + 64, sb + 18432 + 64, sb + 36864 + 64, sb + 55296 + 64,
                      wm * 32, wn * 64, lane, acc);

    const int gid = lane >> 2, tig = lane & 3;
    float srow[2][2] = {{0.f, 0.f}, {0.f, 0.f}};
    #pragma unroll
    for (int mt = 0; mt < 2; mt++) {
        int m = m0 + wm * 32 + mt * 16 + gid;
        float* arow = attn + ((size_t)bh * Sn + m) * Sn;
        #pragma unroll
        for (int nt = 0; nt < 8; nt++) {
            int n = n0 + wn * 64 + nt * 8 + tig * 2;
            float e0 = __expf(acc[mt][nt][0] * 0.125f);
            float e1 = __expf(acc[mt][nt][1] * 0.125f);
            float e2 = __expf(acc[mt][nt][2] * 0.125f);
            float e3 = __expf(acc[mt][nt][3] * 0.125f);
            srow[mt][0] += e0 + e1;
            srow[mt][1] += e2 + e3;
            *(float2*)(arow + n) = make_float2(e0, e1);
            *(float2*)(arow + 8 * Sn + n) = make_float2(e2, e3);
        }
    }
    #pragma unroll
    for (int mt = 0; mt < 2; mt++)
        #pragma unroll
        for (int hh = 0; hh < 2; hh++) {
            srow[mt][hh] += __shfl_xor_sync(0xffffffffu, srow[mt][hh], 1);
            srow[mt][hh] += __shfl_xor_sync(0xffffffffu, srow[mt][hh], 2);
        }
    if (tig == 0) {
        #pragma unroll
        for (int mt = 0; mt < 2; mt++) {
            red[wn * 128 + wm * 32 + mt * 16 + gid]     = srow[mt][0];
            red[wn * 128 + wm * 32 + mt * 16 + gid + 8] = srow[mt][1];
        }
    }
    __syncthreads();
    if (tid < 128)
        g_psum[(((size_t)bh << 10) + m0 + tid) * 8 + blockIdx.x] = red[tid] + red[128 + tid];
}

// ---------------------------------------------------------------------------
// Kernel 3: normalize attn in-place + context = P @ V. grid (8, 128)
// ---------------------------------------------------------------------------
#define AV_SMEM 61952

__global__ void __launch_bounds__(256, 2) av_kernel(float* __restrict__ attn)
{
    extern __shared__ char sm[];
    const uint32_t sb = smem_u32(sm);
    float* inv = (float*)(sm + 61440);

    const int tid = threadIdx.x, lane = tid & 31, wid = tid >> 5;
    const int wm = wid & 3, wn = wid >> 2;
    const int bh = blockIdx.y;
    const int m0 = blockIdx.x * 128;

    if (tid < 128) {
        const float* ps = &g_psum[(((size_t)bh << 10) + m0 + tid) * 8];
        float s = ((ps[0] + ps[1]) + (ps[2] + ps[3])) + ((ps[4] + ps[5]) + (ps[6] + ps[7]));
        inv[tid] = 1.0f / s;
    }

    float* Pb = attn + ((size_t)bh * Sn + m0) * Sn;
    const __nv_bfloat16* Vh = g_vthi + (size_t)bh * Dn * Sn;
    const __nv_bfloat16* Vl = g_vtlo + (size_t)bh * Dn * Sn;

    float4 rv[4];

    float acc[2][4][4];
    #pragma unroll
    for (int i = 0; i < 2; i++)
        #pragma unroll
        for (int j = 0; j < 4; j++)
            #pragma unroll
            for (int l = 0; l < 4; l++) acc[i][j][l] = 0.f;

    // prologue: B chunk 0 + A chunk 0
    {
        int r = tid >> 2, f = tid & 3;
        uint32_t so = (uint32_t)(r * TSTRIDE + f * 16);
        size_t go = (size_t)r * Sn + f * 8;
        cpa16(sb + 40960 + so, Vh + go);
        cpa16(sb + 46080 + so, Vl + go);
    }
    CP_COMMIT();
    #pragma unroll
    for (int j = 0; j < 4; j++) {
        int idx = tid + j * 256;
        int r = idx >> 3, f = idx & 7;
        rv[j] = *(const float4*)(Pb + (size_t)r * Sn + f * 4);
    }
    __syncthreads();   // inv ready
    #pragma unroll
    for (int j = 0; j < 4; j++) {
        int idx = tid + j * 256;
        int r = idx >> 3, f = idx & 7;
        float s = inv[r];
        float4 v = rv[j];
        v.x *= s; v.y *= s; v.z *= s; v.w *= s;
        *(float4*)(Pb + (size_t)r * Sn + f * 4) = v;
        st_hilo(sm, sm + 10240, r, f * 4, v);
    }

    for (int c = 0; c < 32; c++) {
        if (c + 1 < 32) {
            int st = (c + 1) & 1;
            int r = tid >> 2, f = tid & 3;
            uint32_t so = (uint32_t)(r * TSTRIDE + f * 16);
            size_t go = (size_t)r * Sn + (c + 1) * 32 + f * 8;
            cpa16(sb + 40960 + st * 10240 + so, Vh + go);
            cpa16(sb + 46080 + st * 10240 + so, Vl + go);
            CP_COMMIT();
            #pragma unroll
            for (int j = 0; j < 4; j++) {
                int idx = tid + j * 256;
                int rr = idx >> 3, ff = idx & 7;
                rv[j] = *(const float4*)(Pb + (size_t)rr * Sn + (c + 1) * 32 + ff * 4);
            }
            CP_WAIT(1);
        } else {
            CP_WAIT(0);
        }
        __syncthreads();
        uint32_t sa = sb + (c & 1) * 20480;
        uint32_t sv = sb + 40960 + (c & 1) * 10240;
        chunk_mma<4, TSTRIDE>(sa, sa + 10240, sv, sv + 5120, wm * 32, wn * 32, lane, acc);
        __syncthreads();
        if (c + 1 < 32) {
            char* Ah = sm + ((c + 1) & 1) * 20480;
            #pragma unroll
            for (int j = 0; j < 4; j++) {
                int idx = tid + j * 256;
                int r = idx >> 3, f = idx & 7;
                float s = inv[r];
                float4 v = rv[j];
                v.x *= s; v.y *= s; v.z *= s; v.w *= s;
                *(float4*)(Pb + (size_t)r * Sn + (c + 1) * 32 + f * 4) = v;
                st_hilo(Ah, Ah + 10240, r, f * 4, v);
            }
        }
    }

    const int gid = lane >> 2, tig = lane & 3;
    const int bb = bh >> 4, h = bh & 15;
    #pragma unroll
    for (int mt = 0; mt < 2; mt++) {
        int m = m0 + wm * 32 + mt * 16 + gid;
        #pragma unroll
        for (int nt = 0; nt < 4; nt++) {
            int e = h * Dn + wn * 32 + nt * 8 + tig * 2;
            size_t a0 = ((size_t)(bb * Sn + m)) * En + e;
            uint32_t hi, lo;
            split2_u32(acc[mt][nt][0], acc[mt][nt][1], hi, lo);
            *(uint32_t*)(g_chi + a0) = hi; *(uint32_t*)(g_clo + a0) = lo;
            split2_u32(acc[mt][nt][2], acc[mt][nt][3], hi, lo);
            *(uint32_t*)(g_chi + a0 + 8 * En) = hi;
            *(uint32_t*)(g_clo + a0 + 8 * En) = lo;
        }
    }
}

// ---------------------------------------------------------------------------
// Kernel 4: output = ctx @ out_w^T + out_b. grid (8, 64)
// ---------------------------------------------------------------------------
__global__ void __launch_bounds__(256, 2) outproj_kernel(float* __restrict__ Out)
{
    const int tid = threadIdx.x;
    const int m0 = blockIdx.y * 128, n0 = blockIdx.x * 128;
    const __nv_bfloat16* Ah = g_chi + (size_t)m0 * 1024;
    const __nv_bfloat16* Al = g_clo + (size_t)m0 * 1024;
    const __nv_bfloat16* Bh = g_whi + (size_t)3 * W_ELEMS + (size_t)n0 * 1024;
    const __nv_bfloat16* Bl = g_wlo + (size_t)3 * W_ELEMS + (size_t)n0 * 1024;

    gemm_128x128(Ah, Al, Bh, Bl, tid,
        [&](float acc[2][8][4], int wm, int wn, int lane) {
            const int gid = lane >> 2, tig = lane & 3;
            const float* bias = g_bias_ptr[3];
            #pragma unroll
            for (int mt = 0; mt < 2; mt++) {
                int m = m0 + wm * 32 + mt * 16 + gid;
                float* orow = Out + (size_t)m * En;
                #pragma unroll
                for (int nt = 0; nt < 8; nt++) {
                    int n = n0 + wn * 64 + nt * 8 + tig * 2;
                    float2 bv = *(const float2*)(bias + n);
                    *(float2*)(orow + n) =
                        make_float2(acc[mt][nt][0] + bv.x, acc[mt][nt][1] + bv.y);
                    *(float2*)(orow + 8 * En + n) =
                        make_float2(acc[mt][nt][2] + bv.x, acc[mt][nt][3] + bv.y);
                }
            }
        });
}

// ---------------------------------------------------------------------------
extern "C" void kernel_launch(void* const* d_in, const int* in_sizes, int n_in,
                              void* d_out, int out_size)
{
    const float* q_in  = (const float*)d_in[0];
    const float* k_in  = (const float*)d_in[1];
    const float* v_in  = (const float*)d_in[2];
    const float* q_w   = (const float*)d_in[3];
    const float* q_b   = (const float*)d_in[4];
    const float* k_w   = (const float*)d_in[5];
    const float* k_b   = (const float*)d_in[6];
    const float* v_w   = (const float*)d_in[7];
    const float* v_b   = (const float*)d_in[8];
    const float* out_w = (const float*)d_in[9];
    const float* out_b = (const float*)d_in[10];

    float* out  = (float*)d_out;
    float* attn = out;
    float* outp = out + ATTN_ELEMS;

    cudaFuncSetAttribute(proj_kernel,    cudaFuncAttributeMaxDynamicSharedMemorySize, GEMM_SMEM);
    cudaFuncSetAttribute(scores_kernel,  cudaFuncAttributeMaxDynamicSharedMemorySize, SCORES_SMEM);
    cudaFuncSetAttribute(av_kernel,      cudaFuncAttributeMaxDynamicSharedMemorySize, AV_SMEM);
    cudaFuncSetAttribute(outproj_kernel, cudaFuncAttributeMaxDynamicSharedMemorySize, GEMM_SMEM);

    set_bias_kernel<<<1, 1>>>(q_b, k_b, v_b, out_b);
    split_kernel<<<dim3(8192, 7), 256>>>(q_in, k_in, v_in, q_w, k_w, v_w, out_w);
    proj_kernel<<<dim3(8, 64, 3), 256, GEMM_SMEM>>>();
    scores_kernel<<<dim3(8, 8, 128), 256, SCORES_SMEM>>>(attn);
    av_kernel<<<dim3(8, 128), 256, AV_SMEM>>>(attn);
    outproj_kernel<<<dim3(8, 64), 256, GEMM_SMEM>>>(outp);
}

// round 7
// speedup vs baseline: 3.0400x; 1.3370x over previous
#include <cuda_runtime.h>
#include <cuda_fp16.h>
#include <cstdint>

#define Bn 8
#define Sn 1024
#define En 1024
#define Hn 16
#define Dn 64
#define ATTN_ELEMS ((size_t)Bn*Hn*Sn*Sn)
#define IN_ELEMS (Bn*Sn*En)     // 8388608
#define W_ELEMS  (En*En)        // 1048576

// fp16 operand storage (allocation-free rule: __device__ globals)
__device__ __half g_x[3*IN_ELEMS];                     // inputs q,k,v (single)
__device__ __half g_wh[4*W_ELEMS], g_wl[4*W_ELEMS];    // weights hi/lo
__device__ __half g_q[IN_ELEMS];                       // (b,h,s,d) single
__device__ __half g_kh[IN_ELEMS], g_kl[IN_ELEMS];      // (b,h,s,d) hi/lo
__device__ __half g_vth[IN_ELEMS], g_vtl[IN_ELEMS];    // (b,h,d,s) hi/lo
__device__ __half g_ctx[IN_ELEMS];                     // (b,s,e) single

// ---------------- PTX primitives ----------------
__device__ __forceinline__ uint32_t smem_u32(const void* p) {
    uint32_t a;
    asm("{ .reg .u64 t; cvta.to.shared.u64 t, %1; cvt.u32.u64 %0, t; }" : "=r"(a) : "l"(p));
    return a;
}
__device__ __forceinline__ void cpa16(uint32_t sdst, const void* gsrc) {
    asm volatile("cp.async.cg.shared.global [%0], [%1], 16;" :: "r"(sdst), "l"(gsrc));
}
#define CP_COMMIT() asm volatile("cp.async.commit_group;" ::: "memory")
#define CP_WAIT(N)  asm volatile("cp.async.wait_group %0;" :: "n"(N) : "memory")

#define LDSM4(R, A) asm volatile("ldmatrix.sync.aligned.m8n8.x4.shared.b16 {%0,%1,%2,%3}, [%4];" \
    : "=r"((R)[0]), "=r"((R)[1]), "=r"((R)[2]), "=r"((R)[3]) : "r"(A))

__device__ __forceinline__ void mma_f16(float c[4], const uint32_t a[4],
                                        uint32_t b0, uint32_t b1) {
    asm volatile(
        "mma.sync.aligned.m16n8k16.row.col.f32.f16.f16.f32 "
        "{%0,%1,%2,%3}, {%4,%5,%6,%7}, {%8,%9}, {%0,%1,%2,%3};"
        : "+f"(c[0]), "+f"(c[1]), "+f"(c[2]), "+f"(c[3])
        : "r"(a[0]), "r"(a[1]), "r"(a[2]), "r"(a[3]), "r"(b0), "r"(b1));
}

__device__ __forceinline__ uint32_t packh2(float a, float b) {
    __half2 h = __floats2half2_rn(a, b);
    return *(uint32_t*)&h;
}
__device__ __forceinline__ void split1(float x, __half& hi, __half& lo) {
    hi = __float2half_rn(x);
    lo = __float2half_rn(x - __half2float(hi));
}

// ---------------------------------------------------------------------------
// split_kernel: inputs -> fp16 single; weights -> fp16 hi/lo. grid (8192, 7)
// ---------------------------------------------------------------------------
__global__ void __launch_bounds__(256) split_kernel(
    const float* __restrict__ xq, const float* __restrict__ xk, const float* __restrict__ xv,
    const float* __restrict__ wq, const float* __restrict__ wk,
    const float* __restrict__ wv, const float* __restrict__ wo)
{
    const int z = blockIdx.y;
    int i = blockIdx.x * 256 + threadIdx.x;
    if (z < 3) {
        if (i >= IN_ELEMS / 4) return;
        const float* src = (z == 0) ? xq : ((z == 1) ? xk : xv);
        float4 v = ((const float4*)src)[i];
        uint2 o;
        o.x = packh2(v.x, v.y); o.y = packh2(v.z, v.w);
        ((uint2*)(g_x + (size_t)z * IN_ELEMS))[i] = o;
    } else {
        if (i >= W_ELEMS / 4) return;
        const float* src = (z == 3) ? wq : ((z == 4) ? wk : ((z == 5) ? wv : wo));
        float4 v = ((const float4*)src)[i];
        __half h0, l0, h1, l1, h2, l2, h3, l3;
        split1(v.x, h0, l0); split1(v.y, h1, l1);
        split1(v.z, h2, l2); split1(v.w, h3, l3);
        uint2 hi, lo;
        hi.x = packh2(__half2float(h0), __half2float(h1));
        hi.y = packh2(__half2float(h2), __half2float(h3));
        lo.x = packh2(__half2float(l0), __half2float(l1));
        lo.y = packh2(__half2float(l2), __half2float(l3));
        ((uint2*)(g_wh + (size_t)(z - 3) * W_ELEMS))[i] = hi;
        ((uint2*)(g_wl + (size_t)(z - 3) * W_ELEMS))[i] = lo;
    }
}

// ---------------------------------------------------------------------------
// 2-term warp MMA on a K=32 chunk (A single, B hi/lo), stride 80.
// Warp tile: 32 rows x NT*8 cols.
// ---------------------------------------------------------------------------
template<int NT>
__device__ __forceinline__ void chunk2(uint32_t A, uint32_t Bh, uint32_t Bl,
                                       int arow, int bcol, int lane,
                                       float acc[2][NT][4]) {
    const uint32_t aoff = (uint32_t)((arow + (lane & 15)) * 80 + (lane >> 4) * 16);
    const int hb = (lane >> 3) & 3;
    const uint32_t boff = (uint32_t)((bcol + (hb >> 1) * 8 + (lane & 7)) * 80 + (hb & 1) * 16);
    #pragma unroll
    for (int ks = 0; ks < 2; ks++) {
        uint32_t a0[4], a1[4];
        LDSM4(a0, A + aoff + ks * 32);
        LDSM4(a1, A + aoff + 16 * 80 + ks * 32);
        #pragma unroll
        for (int np = 0; np < NT / 2; np++) {
            uint32_t bh4[4], bl4[4];
            LDSM4(bh4, Bh + boff + np * 16 * 80 + ks * 32);
            LDSM4(bl4, Bl + boff + np * 16 * 80 + ks * 32);
            mma_f16(acc[0][2*np],   a0, bh4[0], bh4[1]);
            mma_f16(acc[0][2*np],   a0, bl4[0], bl4[1]);
            mma_f16(acc[1][2*np],   a1, bh4[0], bh4[1]);
            mma_f16(acc[1][2*np],   a1, bl4[0], bl4[1]);
            mma_f16(acc[0][2*np+1], a0, bh4[2], bh4[3]);
            mma_f16(acc[0][2*np+1], a0, bl4[2], bl4[3]);
            mma_f16(acc[1][2*np+1], a1, bh4[2], bh4[3]);
            mma_f16(acc[1][2*np+1], a1, bl4[2], bl4[3]);
        }
    }
}

// ---------------------------------------------------------------------------
// 128x128 GEMM skeleton, K=1024, cp.async 2-stage. A single, B hi/lo.
// stage: A@0 (10240), Bh@10240, Bl@20480 -> 30720; x2 = 61440
// ---------------------------------------------------------------------------
#define PSTG 30720
#define GEMM_SMEM (2*PSTG)

__device__ __forceinline__ void gissue(uint32_t sbase,
    const __half* A, const __half* Bh, const __half* Bl, int tid)
{
    #pragma unroll 2
    for (int idx = tid; idx < 512; idx += 256) {
        int r = idx >> 2, f = idx & 3;
        uint32_t so = (uint32_t)(r * 80 + f * 16);
        size_t go = (size_t)r * 1024 + f * 8;
        cpa16(sbase + so,         A + go);
        cpa16(sbase + 10240 + so, Bh + go);
        cpa16(sbase + 20480 + so, Bl + go);
    }
}

template<typename EPI>
__device__ __forceinline__ void gemm128(
    const __half* A, const __half* Bh, const __half* Bl, int tid, EPI epi)
{
    extern __shared__ char sm[];
    const uint32_t sb = smem_u32(sm);
    const int lane = tid & 31, wid = tid >> 5;
    const int wm = wid & 3, wn = wid >> 2;

    float acc[2][8][4];
    #pragma unroll
    for (int i = 0; i < 2; i++)
        #pragma unroll
        for (int j = 0; j < 8; j++)
            #pragma unroll
            for (int l = 0; l < 4; l++) acc[i][j][l] = 0.f;

    gissue(sb, A, Bh, Bl, tid);
    CP_COMMIT();
    for (int c = 0; c < 32; c++) {
        if (c + 1 < 32) {
            gissue(sb + ((c + 1) & 1) * PSTG,
                   A + (c + 1) * 32, Bh + (c + 1) * 32, Bl + (c + 1) * 32, tid);
            CP_COMMIT();
            CP_WAIT(1);
        } else {
            CP_WAIT(0);
        }
        __syncthreads();
        uint32_t s = sb + (c & 1) * PSTG;
        chunk2<8>(s, s + 10240, s + 20480, wm * 32, wn * 64, lane, acc);
        __syncthreads();
    }
    epi(acc, wm, wn, lane);
}

// ---------------------------------------------------------------------------
// Kernel: QKV projections. grid (8, 64, 3)
// ---------------------------------------------------------------------------
__global__ void __launch_bounds__(256, 2) proj_kernel(
    const float* __restrict__ qb, const float* __restrict__ kb, const float* __restrict__ vb)
{
    const int z = blockIdx.z;
    const int tid = threadIdx.x;
    const int m0 = blockIdx.y * 128, n0 = blockIdx.x * 128;
    const __half* A  = g_x  + (size_t)z * IN_ELEMS + (size_t)m0 * 1024;
    const __half* Bh = g_wh + (size_t)z * W_ELEMS + (size_t)n0 * 1024;
    const __half* Bl = g_wl + (size_t)z * W_ELEMS + (size_t)n0 * 1024;
    const float* bias = (z == 0) ? qb : ((z == 1) ? kb : vb);

    gemm128(A, Bh, Bl, tid,
        [&](float acc[2][8][4], int wm, int wn, int lane) {
            const int g = lane >> 2, t = lane & 3;
            #pragma unroll
            for (int mt = 0; mt < 2; mt++) {
                int m = m0 + wm * 32 + mt * 16 + g;
                int bb = m >> 10, s = m & 1023;
                #pragma unroll
                for (int nt = 0; nt < 8; nt++) {
                    int n = n0 + wn * 64 + nt * 8 + t * 2;
                    int h = n >> 6, d = n & 63;
                    float2 bv = *(const float2*)(bias + n);
                    float c0 = acc[mt][nt][0] + bv.x, c1 = acc[mt][nt][1] + bv.y;
                    float c2 = acc[mt][nt][2] + bv.x, c3 = acc[mt][nt][3] + bv.y;
                    if (z == 0) {
                        size_t a0 = (((size_t)bb * Hn + h) * Sn + s) * Dn + d;
                        *(uint32_t*)(g_q + a0)          = packh2(c0, c1);
                        *(uint32_t*)(g_q + a0 + 8 * Dn) = packh2(c2, c3);
                    } else if (z == 1) {
                        size_t a0 = (((size_t)bb * Hn + h) * Sn + s) * Dn + d;
                        __half h0,l0,h1,l1,h2,l2,h3,l3;
                        split1(c0,h0,l0); split1(c1,h1,l1);
                        split1(c2,h2,l2); split1(c3,h3,l3);
                        *(uint32_t*)(g_kh + a0) = packh2(__half2float(h0), __half2float(h1));
                        *(uint32_t*)(g_kl + a0) = packh2(__half2float(l0), __half2float(l1));
                        *(uint32_t*)(g_kh + a0 + 8 * Dn) = packh2(__half2float(h2), __half2float(h3));
                        *(uint32_t*)(g_kl + a0 + 8 * Dn) = packh2(__half2float(l2), __half2float(l3));
                    } else {
                        // V transposed: (b,h,d,s)
                        size_t a0 = (((size_t)bb * Hn + h) * Dn + d) * Sn + s;
                        __half h0,l0,h1,l1,h2,l2,h3,l3;
                        split1(c0,h0,l0); split1(c1,h1,l1);
                        split1(c2,h2,l2); split1(c3,h3,l3);
                        g_vth[a0] = h0;          g_vtl[a0] = l0;
                        g_vth[a0 + Sn] = h1;     g_vtl[a0 + Sn] = l1;
                        g_vth[a0 + 8] = h2;      g_vtl[a0 + 8] = l2;
                        g_vth[a0 + Sn + 8] = h3; g_vtl[a0 + Sn + 8] = l3;
                    }
                }
            }
        });
}

// ---------------------------------------------------------------------------
// Fused attention: scores + exp + PV + in-place normalize. grid (8, 128)
// Per CTA: (bh, 128-row block). 8 warps x 16 rows. 8 key-chunks of 128.
// smem: Q@0(18432) Kh@18432 Kl@36864 Vh@55296(17408) Vl@72704 sums@90112(512)
// ---------------------------------------------------------------------------
#define FQ 0
#define FKH 18432
#define FKL 36864
#define FVH 55296
#define FVL 72704
#define FSUM 90112
#define FUSED_SMEM 90624

__global__ void __launch_bounds__(256, 2) fused_attn_kernel(float* __restrict__ attn)
{
    extern __shared__ char sm[];
    const uint32_t sb = smem_u32(sm);
    float* sums = (float*)(sm + FSUM);

    const int tid = threadIdx.x, lane = tid & 31, w = tid >> 5;
    const int g = lane >> 2, t = lane & 3;
    const int wr = w * 16;
    const int hb = (lane >> 3) & 3;
    const int m0 = blockIdx.x * 128;
    const int bh = blockIdx.y;

    const __half* Qg  = g_q   + ((size_t)bh * Sn + m0) * Dn;
    const __half* Khg = g_kh  + (size_t)bh * Sn * Dn;
    const __half* Klg = g_kl  + (size_t)bh * Sn * Dn;
    const __half* Vhg = g_vth + (size_t)bh * Dn * Sn;
    const __half* Vlg = g_vtl + (size_t)bh * Dn * Sn;
    float* attnB = attn + ((size_t)bh * Sn + m0) * Sn;

    // Q tile (single fp16): 128 rows x 128B
    #pragma unroll
    for (int j = 0; j < 4; j++) {
        int idx = tid + j * 256;
        int r = idx >> 3, f = idx & 7;
        cpa16(sb + FQ + r * 144 + f * 16, Qg + (size_t)r * Dn + f * 8);
    }
    CP_COMMIT();

    float O[8][4];
    #pragma unroll
    for (int i = 0; i < 8; i++)
        #pragma unroll
        for (int l = 0; l < 4; l++) O[i][l] = 0.f;
    float rs0 = 0.f, rs1 = 0.f;

    for (int c = 0; c < 8; c++) {
        if (c) __syncthreads();            // previous K/V consumed
        // K chunk: 128 key-rows x 128B, hi/lo
        #pragma unroll
        for (int j = 0; j < 4; j++) {
            int idx = tid + j * 256;
            int r = idx >> 3, f = idx & 7;
            size_t go = (size_t)(c * 128 + r) * Dn + f * 8;
            cpa16(sb + FKH + r * 144 + f * 16, Khg + go);
            cpa16(sb + FKL + r * 144 + f * 16, Klg + go);
        }
        // V chunk: 64 d-rows x 256B (s-window), hi/lo
        #pragma unroll
        for (int j = 0; j < 4; j++) {
            int idx = tid + j * 256;
            int d = idx >> 4, f = idx & 15;
            size_t go = (size_t)d * Sn + c * 128 + f * 8;
            cpa16(sb + FVH + d * 272 + f * 16, Vhg + go);
            cpa16(sb + FVL + d * 272 + f * 16, Vlg + go);
        }
        CP_COMMIT();
        CP_WAIT(0);
        __syncthreads();

        #pragma unroll
        for (int sc = 0; sc < 2; sc++) {
            // ---- S = Q K^T over 64-key sub-block (M16 N64 K64) ----
            float sa[8][4];
            #pragma unroll
            for (int i = 0; i < 8; i++)
                #pragma unroll
                for (int l = 0; l < 4; l++) sa[i][l] = 0.f;
            #pragma unroll
            for (int ks = 0; ks < 4; ks++) {
                uint32_t qa[4];
                LDSM4(qa, sb + FQ + (wr + (lane & 15)) * 144 + (lane >> 4) * 16 + ks * 32);
                #pragma unroll
                for (int np = 0; np < 4; np++) {
                    uint32_t bo = (uint32_t)((sc * 64 + np * 16 + (hb >> 1) * 8 + (lane & 7)) * 144
                                             + (hb & 1) * 16 + ks * 32);
                    uint32_t kh4[4], kl4[4];
                    LDSM4(kh4, sb + FKH + bo);
                    LDSM4(kl4, sb + FKL + bo);
                    mma_f16(sa[2*np],   qa, kh4[0], kh4[1]);
                    mma_f16(sa[2*np],   qa, kl4[0], kl4[1]);
                    mma_f16(sa[2*np+1], qa, kh4[2], kh4[3]);
                    mma_f16(sa[2*np+1], qa, kl4[2], kl4[3]);
                }
            }
            // ---- exp, attn write, rowsum ----
            const int cb = c * 128 + sc * 64;
            #pragma unroll
            for (int j = 0; j < 8; j++) {
                float e0 = __expf(sa[j][0] * 0.125f);
                float e1 = __expf(sa[j][1] * 0.125f);
                float e2 = __expf(sa[j][2] * 0.125f);
                float e3 = __expf(sa[j][3] * 0.125f);
                rs0 += e0 + e1; rs1 += e2 + e3;
                *(float2*)(attnB + (size_t)(wr + g) * Sn + cb + j * 8 + t * 2)     = make_float2(e0, e1);
                *(float2*)(attnB + (size_t)(wr + g + 8) * Sn + cb + j * 8 + t * 2) = make_float2(e2, e3);
                sa[j][0] = e0; sa[j][1] = e1; sa[j][2] = e2; sa[j][3] = e3;
            }
            // ---- repack S c-frags -> PV A-frags (fp16 single) ----
            uint32_t PA[4][4];
            #pragma unroll
            for (int i = 0; i < 4; i++) {
                PA[i][0] = packh2(sa[2*i][0],   sa[2*i][1]);
                PA[i][1] = packh2(sa[2*i][2],   sa[2*i][3]);
                PA[i][2] = packh2(sa[2*i+1][0], sa[2*i+1][1]);
                PA[i][3] = packh2(sa[2*i+1][2], sa[2*i+1][3]);
            }
            // ---- O += P V (M16 N64(d) K64(keys)) ----
            #pragma unroll
            for (int ks = 0; ks < 4; ks++) {
                #pragma unroll
                for (int np = 0; np < 4; np++) {
                    uint32_t bo = (uint32_t)((np * 16 + (hb >> 1) * 8 + (lane & 7)) * 272
                                             + (hb & 1) * 16 + sc * 128 + ks * 32);
                    uint32_t vh4[4], vl4[4];
                    LDSM4(vh4, sb + FVH + bo);
                    LDSM4(vl4, sb + FVL + bo);
                    mma_f16(O[2*np],   PA[ks], vh4[0], vh4[1]);
                    mma_f16(O[2*np],   PA[ks], vl4[0], vl4[1]);
                    mma_f16(O[2*np+1], PA[ks], vh4[2], vh4[3]);
                    mma_f16(O[2*np+1], PA[ks], vl4[2], vl4[3]);
                }
            }
        }
    }

    // ---- row sums -> inverses (deterministic fixed-order reduce) ----
    rs0 += __shfl_xor_sync(0xffffffffu, rs0, 1);
    rs0 += __shfl_xor_sync(0xffffffffu, rs0, 2);
    rs1 += __shfl_xor_sync(0xffffffffu, rs1, 1);
    rs1 += __shfl_xor_sync(0xffffffffu, rs1, 2);
    if (t == 0) { sums[wr + g] = rs0; sums[wr + g + 8] = rs1; }
    __syncthreads();
    if (tid < 128) sums[tid] = 1.0f / sums[tid];
    __syncthreads();

    // ---- O epilogue: scale by inv, write ctx fp16 ----
    {
        float i0 = sums[wr + g], i1 = sums[wr + g + 8];
        int m = m0 + wr + g;
        int bb = bh >> 4, h = bh & 15;
        __half* cbase0 = g_ctx + ((size_t)(bb * Sn + m)) * En + h * Dn;
        __half* cbase1 = g_ctx + ((size_t)(bb * Sn + m + 8)) * En + h * Dn;
        #pragma unroll
        for (int nt = 0; nt < 8; nt++) {
            int d = nt * 8 + t * 2;
            *(uint32_t*)(cbase0 + d) = packh2(O[nt][0] * i0, O[nt][1] * i0);
            *(uint32_t*)(cbase1 + d) = packh2(O[nt][2] * i1, O[nt][3] * i1);
        }
    }

    // ---- normalize attn in place (own block; L2-hot) ----
    for (int j = 0; j < 128; j++) {
        float iv = sums[j];
        float4* p = (float4*)(attnB + (size_t)j * Sn) + tid;
        float4 v = *p;
        v.x *= iv; v.y *= iv; v.z *= iv; v.w *= iv;
        *p = v;
    }
}

// ---------------------------------------------------------------------------
// Kernel: output projection. grid (8, 64)
// ---------------------------------------------------------------------------
__global__ void __launch_bounds__(256, 2) outproj_kernel(
    const float* __restrict__ ob, float* __restrict__ Out)
{
    const int tid = threadIdx.x;
    const int m0 = blockIdx.y * 128, n0 = blockIdx.x * 128;
    const __half* A  = g_ctx + (size_t)m0 * 1024;
    const __half* Bh = g_wh + (size_t)3 * W_ELEMS + (size_t)n0 * 1024;
    const __half* Bl = g_wl + (size_t)3 * W_ELEMS + (size_t)n0 * 1024;

    gemm128(A, Bh, Bl, tid,
        [&](float acc[2][8][4], int wm, int wn, int lane) {
            const int g = lane >> 2, t = lane & 3;
            #pragma unroll
            for (int mt = 0; mt < 2; mt++) {
                int m = m0 + wm * 32 + mt * 16 + g;
                float* orow = Out + (size_t)m * En;
                #pragma unroll
                for (int nt = 0; nt < 8; nt++) {
                    int n = n0 + wn * 64 + nt * 8 + t * 2;
                    float2 bv = *(const float2*)(ob + n);
                    *(float2*)(orow + n) =
                        make_float2(acc[mt][nt][0] + bv.x, acc[mt][nt][1] + bv.y);
                    *(float2*)(orow + 8 * En + n) =
                        make_float2(acc[mt][nt][2] + bv.x, acc[mt][nt][3] + bv.y);
                }
            }
        });
}

// ---------------------------------------------------------------------------
extern "C" void kernel_launch(void* const* d_in, const int* in_sizes, int n_in,
                              void* d_out, int out_size)
{
    const float* q_in  = (const float*)d_in[0];
    const float* k_in  = (const float*)d_in[1];
    const float* v_in  = (const float*)d_in[2];
    const float* q_w   = (const float*)d_in[3];
    const float* q_b   = (const float*)d_in[4];
    const float* k_w   = (const float*)d_in[5];
    const float* k_b   = (const float*)d_in[6];
    const float* v_w   = (const float*)d_in[7];
    const float* v_b   = (const float*)d_in[8];
    const float* out_w = (const float*)d_in[9];
    const float* out_b = (const float*)d_in[10];

    float* out  = (float*)d_out;
    float* attn = out;                  // (B,H,S,S)
    float* outp = out + ATTN_ELEMS;     // (B,S,E)

    cudaFuncSetAttribute(proj_kernel,       cudaFuncAttributeMaxDynamicSharedMemorySize, GEMM_SMEM);
    cudaFuncSetAttribute(fused_attn_kernel, cudaFuncAttributeMaxDynamicSharedMemorySize, FUSED_SMEM);
    cudaFuncSetAttribute(outproj_kernel,    cudaFuncAttributeMaxDynamicSharedMemorySize, GEMM_SMEM);

    split_kernel<<<dim3(8192, 7), 256>>>(q_in, k_in, v_in, q_w, k_w, v_w, out_w);
    proj_kernel<<<dim3(8, 64, 3), 256, GEMM_SMEM>>>(q_b, k_b, v_b);
    fused_attn_kernel<<<dim3(8, 128), 256, FUSED_SMEM>>>(attn);
    outproj_kernel<<<dim3(8, 64), 256, GEMM_SMEM>>>(out_b, outp);
}

// round 8
// speedup vs baseline: 3.2013x; 1.0531x over previous
#include <cuda_runtime.h>
#include <cuda_fp16.h>
#include <cstdint>

#define Bn 8
#define Sn 1024
#define En 1024
#define Hn 16
#define Dn 64
#define ATTN_ELEMS ((size_t)Bn*Hn*Sn*Sn)
#define IN_ELEMS (Bn*Sn*En)     // 8388608
#define W_ELEMS  (En*En)        // 1048576

// fp16 operand storage (allocation-free rule: __device__ globals)
__device__ __half g_x[3*IN_ELEMS];                     // inputs q,k,v (single)
__device__ __half g_wh[4*W_ELEMS], g_wl[4*W_ELEMS];    // weights hi/lo
__device__ __half g_q[IN_ELEMS];                       // (b,h,s,d) single
__device__ __half g_kh[IN_ELEMS], g_kl[IN_ELEMS];      // (b,h,s,d) hi/lo
__device__ __half g_vth[IN_ELEMS], g_vtl[IN_ELEMS];    // (b,h,d,s) hi/lo
__device__ __half g_ctx[IN_ELEMS];                     // (b,s,e) single

// ---------------- PTX primitives ----------------
__device__ __forceinline__ uint32_t smem_u32(const void* p) {
    uint32_t a;
    asm("{ .reg .u64 t; cvta.to.shared.u64 t, %1; cvt.u32.u64 %0, t; }" : "=r"(a) : "l"(p));
    return a;
}
__device__ __forceinline__ void cpa16(uint32_t sdst, const void* gsrc) {
    asm volatile("cp.async.cg.shared.global [%0], [%1], 16;" :: "r"(sdst), "l"(gsrc));
}
#define CP_COMMIT() asm volatile("cp.async.commit_group;" ::: "memory")
#define CP_WAIT(N)  asm volatile("cp.async.wait_group %0;" :: "n"(N) : "memory")

#define LDSM4(R, A) asm volatile("ldmatrix.sync.aligned.m8n8.x4.shared.b16 {%0,%1,%2,%3}, [%4];" \
    : "=r"((R)[0]), "=r"((R)[1]), "=r"((R)[2]), "=r"((R)[3]) : "r"(A))

__device__ __forceinline__ void mma_f16(float c[4], const uint32_t a[4],
                                        uint32_t b0, uint32_t b1) {
    asm volatile(
        "mma.sync.aligned.m16n8k16.row.col.f32.f16.f16.f32 "
        "{%0,%1,%2,%3}, {%4,%5,%6,%7}, {%8,%9}, {%0,%1,%2,%3};"
        : "+f"(c[0]), "+f"(c[1]), "+f"(c[2]), "+f"(c[3])
        : "r"(a[0]), "r"(a[1]), "r"(a[2]), "r"(a[3]), "r"(b0), "r"(b1));
}

__device__ __forceinline__ uint32_t packh2(float a, float b) {
    __half2 h = __floats2half2_rn(a, b);
    return *(uint32_t*)&h;
}
__device__ __forceinline__ void split1(float x, __half& hi, __half& lo) {
    hi = __float2half_rn(x);
    lo = __float2half_rn(x - __half2float(hi));
}

// ---------------------------------------------------------------------------
// split_kernel: inputs -> fp16 single; weights -> fp16 hi/lo. grid (8192, 7)
// ---------------------------------------------------------------------------
__global__ void __launch_bounds__(256) split_kernel(
    const float* __restrict__ xq, const float* __restrict__ xk, const float* __restrict__ xv,
    const float* __restrict__ wq, const float* __restrict__ wk,
    const float* __restrict__ wv, const float* __restrict__ wo)
{
    const int z = blockIdx.y;
    int i = blockIdx.x * 256 + threadIdx.x;
    if (z < 3) {
        if (i >= IN_ELEMS / 4) return;
        const float* src = (z == 0) ? xq : ((z == 1) ? xk : xv);
        float4 v = ((const float4*)src)[i];
        uint2 o;
        o.x = packh2(v.x, v.y); o.y = packh2(v.z, v.w);
        ((uint2*)(g_x + (size_t)z * IN_ELEMS))[i] = o;
    } else {
        if (i >= W_ELEMS / 4) return;
        const float* src = (z == 3) ? wq : ((z == 4) ? wk : ((z == 5) ? wv : wo));
        float4 v = ((const float4*)src)[i];
        __half h0, l0, h1, l1, h2, l2, h3, l3;
        split1(v.x, h0, l0); split1(v.y, h1, l1);
        split1(v.z, h2, l2); split1(v.w, h3, l3);
        uint2 hi, lo;
        hi.x = packh2(__half2float(h0), __half2float(h1));
        hi.y = packh2(__half2float(h2), __half2float(h3));
        lo.x = packh2(__half2float(l0), __half2float(l1));
        lo.y = packh2(__half2float(l2), __half2float(l3));
        ((uint2*)(g_wh + (size_t)(z - 3) * W_ELEMS))[i] = hi;
        ((uint2*)(g_wl + (size_t)(z - 3) * W_ELEMS))[i] = lo;
    }
}

// ---------------------------------------------------------------------------
// 2-term warp MMA on a K=32 chunk (A single, B hi/lo), stride 80.
// ---------------------------------------------------------------------------
template<int NT>
__device__ __forceinline__ void chunk2(uint32_t A, uint32_t Bh, uint32_t Bl,
                                       int arow, int bcol, int lane,
                                       float acc[2][NT][4]) {
    const uint32_t aoff = (uint32_t)((arow + (lane & 15)) * 80 + (lane >> 4) * 16);
    const int hb = (lane >> 3) & 3;
    const uint32_t boff = (uint32_t)((bcol + (hb >> 1) * 8 + (lane & 7)) * 80 + (hb & 1) * 16);
    #pragma unroll
    for (int ks = 0; ks < 2; ks++) {
        uint32_t a0[4], a1[4];
        LDSM4(a0, A + aoff + ks * 32);
        LDSM4(a1, A + aoff + 16 * 80 + ks * 32);
        #pragma unroll
        for (int np = 0; np < NT / 2; np++) {
            uint32_t bh4[4], bl4[4];
            LDSM4(bh4, Bh + boff + np * 16 * 80 + ks * 32);
            LDSM4(bl4, Bl + boff + np * 16 * 80 + ks * 32);
            mma_f16(acc[0][2*np],   a0, bh4[0], bh4[1]);
            mma_f16(acc[0][2*np],   a0, bl4[0], bl4[1]);
            mma_f16(acc[1][2*np],   a1, bh4[0], bh4[1]);
            mma_f16(acc[1][2*np],   a1, bl4[0], bl4[1]);
            mma_f16(acc[0][2*np+1], a0, bh4[2], bh4[3]);
            mma_f16(acc[0][2*np+1], a0, bl4[2], bl4[3]);
            mma_f16(acc[1][2*np+1], a1, bh4[2], bh4[3]);
            mma_f16(acc[1][2*np+1], a1, bl4[2], bl4[3]);
        }
    }
}

// ---------------------------------------------------------------------------
// 128x128 GEMM, K=1024, 2-stage cp.async, SINGLE sync per chunk:
//   wait(0) -> sync -> issue(c+1) -> compute(c).
// After the sync all warps finished chunk c-1, so writing stage (c+1)&1
// (= stage (c-1)&1) cannot race readers. Load c+1 overlaps compute c.
// ---------------------------------------------------------------------------
#define PSTG 30720
#define GEMM_SMEM (2*PSTG)

__device__ __forceinline__ void gissue(uint32_t sbase,
    const __half* A, const __half* Bh, const __half* Bl, int tid)
{
    #pragma unroll 2
    for (int idx = tid; idx < 512; idx += 256) {
        int r = idx >> 2, f = idx & 3;
        uint32_t so = (uint32_t)(r * 80 + f * 16);
        size_t go = (size_t)r * 1024 + f * 8;
        cpa16(sbase + so,         A + go);
        cpa16(sbase + 10240 + so, Bh + go);
        cpa16(sbase + 20480 + so, Bl + go);
    }
}

template<typename EPI>
__device__ __forceinline__ void gemm128(
    const __half* A, const __half* Bh, const __half* Bl, int tid, EPI epi)
{
    extern __shared__ char sm[];
    const uint32_t sb = smem_u32(sm);
    const int lane = tid & 31, wid = tid >> 5;
    const int wm = wid & 3, wn = wid >> 2;

    float acc[2][8][4];
    #pragma unroll
    for (int i = 0; i < 2; i++)
        #pragma unroll
        for (int j = 0; j < 8; j++)
            #pragma unroll
            for (int l = 0; l < 4; l++) acc[i][j][l] = 0.f;

    gissue(sb, A, Bh, Bl, tid);
    CP_COMMIT();
    for (int c = 0; c < 32; c++) {
        CP_WAIT(0);
        __syncthreads();
        if (c + 1 < 32) {
            gissue(sb + ((c + 1) & 1) * PSTG,
                   A + (c + 1) * 32, Bh + (c + 1) * 32, Bl + (c + 1) * 32, tid);
            CP_COMMIT();
        }
        uint32_t s = sb + (c & 1) * PSTG;
        chunk2<8>(s, s + 10240, s + 20480, wm * 32, wn * 64, lane, acc);
    }
    epi(acc, wm, wn, lane);
}

// ---------------------------------------------------------------------------
// Kernel: QKV projections. grid (8, 64, 3)
// ---------------------------------------------------------------------------
__global__ void __launch_bounds__(256, 2) proj_kernel(
    const float* __restrict__ qb, const float* __restrict__ kb, const float* __restrict__ vb)
{
    const int z = blockIdx.z;
    const int tid = threadIdx.x;
    const int m0 = blockIdx.y * 128, n0 = blockIdx.x * 128;
    const __half* A  = g_x  + (size_t)z * IN_ELEMS + (size_t)m0 * 1024;
    const __half* Bh = g_wh + (size_t)z * W_ELEMS + (size_t)n0 * 1024;
    const __half* Bl = g_wl + (size_t)z * W_ELEMS + (size_t)n0 * 1024;
    const float* bias = (z == 0) ? qb : ((z == 1) ? kb : vb);

    gemm128(A, Bh, Bl, tid,
        [&](float acc[2][8][4], int wm, int wn, int lane) {
            const int g = lane >> 2, t = lane & 3;
            #pragma unroll
            for (int mt = 0; mt < 2; mt++) {
                int m = m0 + wm * 32 + mt * 16 + g;
                int bb = m >> 10, s = m & 1023;
                #pragma unroll
                for (int nt = 0; nt < 8; nt++) {
                    int n = n0 + wn * 64 + nt * 8 + t * 2;
                    int h = n >> 6, d = n & 63;
                    float2 bv = *(const float2*)(bias + n);
                    float c0 = acc[mt][nt][0] + bv.x, c1 = acc[mt][nt][1] + bv.y;
                    float c2 = acc[mt][nt][2] + bv.x, c3 = acc[mt][nt][3] + bv.y;
                    if (z == 0) {
                        size_t a0 = (((size_t)bb * Hn + h) * Sn + s) * Dn + d;
                        *(uint32_t*)(g_q + a0)          = packh2(c0, c1);
                        *(uint32_t*)(g_q + a0 + 8 * Dn) = packh2(c2, c3);
                    } else if (z == 1) {
                        size_t a0 = (((size_t)bb * Hn + h) * Sn + s) * Dn + d;
                        __half h0,l0,h1,l1,h2,l2,h3,l3;
                        split1(c0,h0,l0); split1(c1,h1,l1);
                        split1(c2,h2,l2); split1(c3,h3,l3);
                        *(uint32_t*)(g_kh + a0) = packh2(__half2float(h0), __half2float(h1));
                        *(uint32_t*)(g_kl + a0) = packh2(__half2float(l0), __half2float(l1));
                        *(uint32_t*)(g_kh + a0 + 8 * Dn) = packh2(__half2float(h2), __half2float(h3));
                        *(uint32_t*)(g_kl + a0 + 8 * Dn) = packh2(__half2float(l2), __half2float(l3));
                    } else {
                        // V transposed: (b,h,d,s)
                        size_t a0 = (((size_t)bb * Hn + h) * Dn + d) * Sn + s;
                        __half h0,l0,h1,l1,h2,l2,h3,l3;
                        split1(c0,h0,l0); split1(c1,h1,l1);
                        split1(c2,h2,l2); split1(c3,h3,l3);
                        g_vth[a0] = h0;          g_vtl[a0] = l0;
                        g_vth[a0 + Sn] = h1;     g_vtl[a0 + Sn] = l1;
                        g_vth[a0 + 8] = h2;      g_vtl[a0 + 8] = l2;
                        g_vth[a0 + Sn + 8] = h3; g_vtl[a0 + Sn + 8] = l3;
                    }
                }
            }
        });
}

// ---------------------------------------------------------------------------
// Fused attention: scores + exp + PV + in-place normalize. grid (8, 128)
// 16 key-chunks of 64, 2-stage double-buffered K/V, single sync per chunk.
// smem: Q@0 (18432) | stage st @ 18432+st*36864: KH+0 KL+9216 VH+18432 VL+27648
//       sums @ 92160 (512) -> total 92672 (x2 CTAs = 185344 <= 227KB)
// ---------------------------------------------------------------------------
#define FQ 0
#define FST(st) (18432 + (st)*36864)
#define FSUM 92160
#define FUSED_SMEM 92672

__global__ void __launch_bounds__(256, 2) fused_attn_kernel(float* __restrict__ attn)
{
    extern __shared__ char sm[];
    const uint32_t sb = smem_u32(sm);
    float* sums = (float*)(sm + FSUM);

    const int tid = threadIdx.x, lane = tid & 31, w = tid >> 5;
    const int g = lane >> 2, t = lane & 3;
    const int wr = w * 16;
    const int hb = (lane >> 3) & 3;
    const int m0 = blockIdx.x * 128;
    const int bh = blockIdx.y;

    const __half* Qg  = g_q   + ((size_t)bh * Sn + m0) * Dn;
    const __half* Khg = g_kh  + (size_t)bh * Sn * Dn;
    const __half* Klg = g_kl  + (size_t)bh * Sn * Dn;
    const __half* Vhg = g_vth + (size_t)bh * Dn * Sn;
    const __half* Vlg = g_vtl + (size_t)bh * Dn * Sn;
    float* attnB = attn + ((size_t)bh * Sn + m0) * Sn;

    auto issueKV = [&](int c, int st) {
        uint32_t base = sb + FST(st);
        #pragma unroll
        for (int j = 0; j < 2; j++) {
            int idx = tid + j * 256;           // 512: 64 key-rows x 8 frags
            int r = idx >> 3, f = idx & 7;
            size_t go = (size_t)(c * 64 + r) * Dn + f * 8;
            cpa16(base + r * 144 + f * 16,        Khg + go);
            cpa16(base + 9216 + r * 144 + f * 16, Klg + go);
        }
        #pragma unroll
        for (int j = 0; j < 2; j++) {
            int idx = tid + j * 256;           // 512: 64 d-rows x 8 frags
            int d = idx >> 3, f = idx & 7;
            size_t go = (size_t)d * Sn + c * 64 + f * 8;
            cpa16(base + 18432 + d * 144 + f * 16, Vhg + go);
            cpa16(base + 27648 + d * 144 + f * 16, Vlg + go);
        }
    };

    // prologue: Q tile + chunk 0 (one group)
    #pragma unroll
    for (int j = 0; j < 4; j++) {
        int idx = tid + j * 256;
        int r = idx >> 3, f = idx & 7;
        cpa16(sb + FQ + r * 144 + f * 16, Qg + (size_t)r * Dn + f * 8);
    }
    issueKV(0, 0);
    CP_COMMIT();

    float O[8][4];
    #pragma unroll
    for (int i = 0; i < 8; i++)
        #pragma unroll
        for (int l = 0; l < 4; l++) O[i][l] = 0.f;
    float rs0 = 0.f, rs1 = 0.f;

    for (int c = 0; c < 16; c++) {
        CP_WAIT(0);
        __syncthreads();
        if (c + 1 < 16) {
            issueKV(c + 1, (c + 1) & 1);
            CP_COMMIT();
        }
        const uint32_t stg = sb + FST(c & 1);

        // ---- S = Q K^T (M16 x N64keys x K64d), 2-term on K ----
        float sa[8][4];
        #pragma unroll
        for (int i = 0; i < 8; i++)
            #pragma unroll
            for (int l = 0; l < 4; l++) sa[i][l] = 0.f;
        #pragma unroll
        for (int ks = 0; ks < 4; ks++) {
            uint32_t qa[4];
            LDSM4(qa, sb + FQ + (wr + (lane & 15)) * 144 + (lane >> 4) * 16 + ks * 32);
            #pragma unroll
            for (int np = 0; np < 4; np++) {
                uint32_t bo = (uint32_t)((np * 16 + (hb >> 1) * 8 + (lane & 7)) * 144
                                         + (hb & 1) * 16 + ks * 32);
                uint32_t kh4[4], kl4[4];
                LDSM4(kh4, stg + bo);
                LDSM4(kl4, stg + 9216 + bo);
                mma_f16(sa[2*np],   qa, kh4[0], kh4[1]);
                mma_f16(sa[2*np],   qa, kl4[0], kl4[1]);
                mma_f16(sa[2*np+1], qa, kh4[2], kh4[3]);
                mma_f16(sa[2*np+1], qa, kl4[2], kl4[3]);
            }
        }
        // ---- exp, attn write (unnormalized), rowsum ----
        const int cb = c * 64;
        #pragma unroll
        for (int j = 0; j < 8; j++) {
            float e0 = __expf(sa[j][0] * 0.125f);
            float e1 = __expf(sa[j][1] * 0.125f);
            float e2 = __expf(sa[j][2] * 0.125f);
            float e3 = __expf(sa[j][3] * 0.125f);
            rs0 += e0 + e1; rs1 += e2 + e3;
            *(float2*)(attnB + (size_t)(wr + g) * Sn + cb + j * 8 + t * 2)     = make_float2(e0, e1);
            *(float2*)(attnB + (size_t)(wr + g + 8) * Sn + cb + j * 8 + t * 2) = make_float2(e2, e3);
            sa[j][0] = e0; sa[j][1] = e1; sa[j][2] = e2; sa[j][3] = e3;
        }
        // ---- repack S c-frags -> PV A-frags (fp16) ----
        uint32_t PA[4][4];
        #pragma unroll
        for (int i = 0; i < 4; i++) {
            PA[i][0] = packh2(sa[2*i][0],   sa[2*i][1]);
            PA[i][1] = packh2(sa[2*i][2],   sa[2*i][3]);
            PA[i][2] = packh2(sa[2*i+1][0], sa[2*i+1][1]);
            PA[i][3] = packh2(sa[2*i+1][2], sa[2*i+1][3]);
        }
        // ---- O += P V (M16 x N64d x K64keys), 2-term on V ----
        #pragma unroll
        for (int ks = 0; ks < 4; ks++) {
            #pragma unroll
            for (int np = 0; np < 4; np++) {
                uint32_t bo = (uint32_t)((np * 16 + (hb >> 1) * 8 + (lane & 7)) * 144
                                         + (hb & 1) * 16 + ks * 32);
                uint32_t vh4[4], vl4[4];
                LDSM4(vh4, stg + 18432 + bo);
                LDSM4(vl4, stg + 27648 + bo);
                mma_f16(O[2*np],   PA[ks], vh4[0], vh4[1]);
                mma_f16(O[2*np],   PA[ks], vl4[0], vl4[1]);
                mma_f16(O[2*np+1], PA[ks], vh4[2], vh4[3]);
                mma_f16(O[2*np+1], PA[ks], vl4[2], vl4[3]);
            }
        }
    }

    // ---- row sums -> inverses (deterministic fixed-order reduce) ----
    rs0 += __shfl_xor_sync(0xffffffffu, rs0, 1);
    rs0 += __shfl_xor_sync(0xffffffffu, rs0, 2);
    rs1 += __shfl_xor_sync(0xffffffffu, rs1, 1);
    rs1 += __shfl_xor_sync(0xffffffffu, rs1, 2);
    if (t == 0) { sums[wr + g] = rs0; sums[wr + g + 8] = rs1; }
    __syncthreads();
    if (tid < 128) sums[tid] = 1.0f / sums[tid];
    __syncthreads();

    // ---- O epilogue: scale by inv, write ctx fp16 ----
    {
        float i0 = sums[wr + g], i1 = sums[wr + g + 8];
        int m = m0 + wr + g;
        int bb = bh >> 4, h = bh & 15;
        __half* cbase0 = g_ctx + ((size_t)(bb * Sn + m)) * En + h * Dn;
        __half* cbase1 = g_ctx + ((size_t)(bb * Sn + m + 8)) * En + h * Dn;
        #pragma unroll
        for (int nt = 0; nt < 8; nt++) {
            int d = nt * 8 + t * 2;
            *(uint32_t*)(cbase0 + d) = packh2(O[nt][0] * i0, O[nt][1] * i0);
            *(uint32_t*)(cbase1 + d) = packh2(O[nt][2] * i1, O[nt][3] * i1);
        }
    }

    // ---- normalize attn in place ----
    for (int j = 0; j < 128; j++) {
        float iv = sums[j];
        float4* p = (float4*)(attnB + (size_t)j * Sn) + tid;
        float4 v = *p;
        v.x *= iv; v.y *= iv; v.z *= iv; v.w *= iv;
        *p = v;
    }
}

// ---------------------------------------------------------------------------
// Kernel: output projection. grid (8, 64)
// ---------------------------------------------------------------------------
__global__ void __launch_bounds__(256, 2) outproj_kernel(
    const float* __restrict__ ob, float* __restrict__ Out)
{
    const int tid = threadIdx.x;
    const int m0 = blockIdx.y * 128, n0 = blockIdx.x * 128;
    const __half* A  = g_ctx + (size_t)m0 * 1024;
    const __half* Bh = g_wh + (size_t)3 * W_ELEMS + (size_t)n0 * 1024;
    const __half* Bl = g_wl + (size_t)3 * W_ELEMS + (size_t)n0 * 1024;

    gemm128(A, Bh, Bl, tid,
        [&](float acc[2][8][4], int wm, int wn, int lane) {
            const int g = lane >> 2, t = lane & 3;
            #pragma unroll
            for (int mt = 0; mt < 2; mt++) {
                int m = m0 + wm * 32 + mt * 16 + g;
                float* orow = Out + (size_t)m * En;
                #pragma unroll
                for (int nt = 0; nt < 8; nt++) {
                    int n = n0 + wn * 64 + nt * 8 + t * 2;
                    float2 bv = *(const float2*)(ob + n);
                    *(float2*)(orow + n) =
                        make_float2(acc[mt][nt][0] + bv.x, acc[mt][nt][1] + bv.y);
                    *(float2*)(orow + 8 * En + n) =
                        make_float2(acc[mt][nt][2] + bv.x, acc[mt][nt][3] + bv.y);
                }
            }
        });
}

// ---------------------------------------------------------------------------
extern "C" void kernel_launch(void* const* d_in, const int* in_sizes, int n_in,
                              void* d_out, int out_size)
{
    const float* q_in  = (const float*)d_in[0];
    const float* k_in  = (const float*)d_in[1];
    const float* v_in  = (const float*)d_in[2];
    const float* q_w   = (const float*)d_in[3];
    const float* q_b   = (const float*)d_in[4];
    const float* k_w   = (const float*)d_in[5];
    const float* k_b   = (const float*)d_in[6];
    const float* v_w   = (const float*)d_in[7];
    const float* v_b   = (const float*)d_in[8];
    const float* out_w = (const float*)d_in[9];
    const float* out_b = (const float*)d_in[10];

    float* out  = (float*)d_out;
    float* attn = out;                  // (B,H,S,S)
    float* outp = out + ATTN_ELEMS;     // (B,S,E)

    cudaFuncSetAttribute(proj_kernel,       cudaFuncAttributeMaxDynamicSharedMemorySize, GEMM_SMEM);
    cudaFuncSetAttribute(fused_attn_kernel, cudaFuncAttributeMaxDynamicSharedMemorySize, FUSED_SMEM);
    cudaFuncSetAttribute(outproj_kernel,    cudaFuncAttributeMaxDynamicSharedMemorySize, GEMM_SMEM);

    split_kernel<<<dim3(8192, 7), 256>>>(q_in, k_in, v_in, q_w, k_w, v_w, out_w);
    proj_kernel<<<dim3(8, 64, 3), 256, GEMM_SMEM>>>(q_b, k_b, v_b);
    fused_attn_kernel<<<dim3(8, 128), 256, FUSED_SMEM>>>(attn);
    outproj_kernel<<<dim3(8, 64), 256, GEMM_SMEM>>>(out_b, outp);
}

// round 9
// speedup vs baseline: 3.3879x; 1.0583x over previous
#include <cuda_runtime.h>
#include <cuda_fp16.h>
#include <cstdint>

#define Bn 8
#define Sn 1024
#define En 1024
#define Hn 16
#define Dn 64
#define ATTN_ELEMS ((size_t)Bn*Hn*Sn*Sn)
#define IN_ELEMS (Bn*Sn*En)     // 8388608
#define W_ELEMS  (En*En)        // 1048576

// fp16 operand storage (allocation-free rule: __device__ globals)
__device__ __half g_x[3*IN_ELEMS];                     // inputs q,k,v (single)
__device__ __half g_wh[4*W_ELEMS], g_wl[4*W_ELEMS];    // weights hi/lo
__device__ __half g_q[IN_ELEMS];                       // (b,h,s,d) single
__device__ __half g_kh[IN_ELEMS], g_kl[IN_ELEMS];      // (b,h,s,d) hi/lo
__device__ __half g_vth[IN_ELEMS], g_vtl[IN_ELEMS];    // (b,h,d,s) hi/lo
__device__ __half g_ctx[IN_ELEMS];                     // (b,s,e) single
__device__ float g_inv[Bn*Hn*Sn];                      // softmax 1/rowsum

// ---------------- PTX primitives ----------------
__device__ __forceinline__ uint32_t smem_u32(const void* p) {
    uint32_t a;
    asm("{ .reg .u64 t; cvta.to.shared.u64 t, %1; cvt.u32.u64 %0, t; }" : "=r"(a) : "l"(p));
    return a;
}
__device__ __forceinline__ void cpa16(uint32_t sdst, const void* gsrc) {
    asm volatile("cp.async.cg.shared.global [%0], [%1], 16;" :: "r"(sdst), "l"(gsrc));
}
#define CP_COMMIT() asm volatile("cp.async.commit_group;" ::: "memory")
#define CP_WAIT(N)  asm volatile("cp.async.wait_group %0;" :: "n"(N) : "memory")

#define LDSM4(R, A) asm volatile("ldmatrix.sync.aligned.m8n8.x4.shared.b16 {%0,%1,%2,%3}, [%4];" \
    : "=r"((R)[0]), "=r"((R)[1]), "=r"((R)[2]), "=r"((R)[3]) : "r"(A))

__device__ __forceinline__ void mma_f16(float c[4], const uint32_t a[4],
                                        uint32_t b0, uint32_t b1) {
    asm volatile(
        "mma.sync.aligned.m16n8k16.row.col.f32.f16.f16.f32 "
        "{%0,%1,%2,%3}, {%4,%5,%6,%7}, {%8,%9}, {%0,%1,%2,%3};"
        : "+f"(c[0]), "+f"(c[1]), "+f"(c[2]), "+f"(c[3])
        : "r"(a[0]), "r"(a[1]), "r"(a[2]), "r"(a[3]), "r"(b0), "r"(b1));
}

__device__ __forceinline__ uint32_t packh2(float a, float b) {
    __half2 h = __floats2half2_rn(a, b);
    return *(uint32_t*)&h;
}
__device__ __forceinline__ void split1(float x, __half& hi, __half& lo) {
    hi = __float2half_rn(x);
    lo = __float2half_rn(x - __half2float(hi));
}

// ---------------------------------------------------------------------------
// split_kernel: inputs -> fp16 single; weights -> fp16 hi/lo. grid (8192, 7)
// ---------------------------------------------------------------------------
__global__ void __launch_bounds__(256) split_kernel(
    const float* __restrict__ xq, const float* __restrict__ xk, const float* __restrict__ xv,
    const float* __restrict__ wq, const float* __restrict__ wk,
    const float* __restrict__ wv, const float* __restrict__ wo)
{
    const int z = blockIdx.y;
    int i = blockIdx.x * 256 + threadIdx.x;
    if (z < 3) {
        if (i >= IN_ELEMS / 4) return;
        const float* src = (z == 0) ? xq : ((z == 1) ? xk : xv);
        float4 v = ((const float4*)src)[i];
        uint2 o;
        o.x = packh2(v.x, v.y); o.y = packh2(v.z, v.w);
        ((uint2*)(g_x + (size_t)z * IN_ELEMS))[i] = o;
    } else {
        if (i >= W_ELEMS / 4) return;
        const float* src = (z == 3) ? wq : ((z == 4) ? wk : ((z == 5) ? wv : wo));
        float4 v = ((const float4*)src)[i];
        __half h0, l0, h1, l1, h2, l2, h3, l3;
        split1(v.x, h0, l0); split1(v.y, h1, l1);
        split1(v.z, h2, l2); split1(v.w, h3, l3);
        uint2 hi, lo;
        hi.x = packh2(__half2float(h0), __half2float(h1));
        hi.y = packh2(__half2float(h2), __half2float(h3));
        lo.x = packh2(__half2float(l0), __half2float(l1));
        lo.y = packh2(__half2float(l2), __half2float(l3));
        ((uint2*)(g_wh + (size_t)(z - 3) * W_ELEMS))[i] = hi;
        ((uint2*)(g_wl + (size_t)(z - 3) * W_ELEMS))[i] = lo;
    }
}

// ---------------------------------------------------------------------------
// 2-term warp MMA on a K=32 chunk (A single, B hi/lo), stride 80.
// Warp tile 64 rows x 32 cols (wm=2, wn=4): B read by 2 warps (was 4),
// 16 LDSM4/chunk (was 20) -> -20% smem traffic for identical MMA count.
// ---------------------------------------------------------------------------
__device__ __forceinline__ void chunk2(uint32_t A, uint32_t Bh, uint32_t Bl,
                                       int arow, int bcol, int lane,
                                       float acc[4][4][4]) {
    const int hb = (lane >> 3) & 3;
    const uint32_t abase = (uint32_t)((arow + (lane & 15)) * 80 + (lane >> 4) * 16);
    const uint32_t bbase = (uint32_t)((bcol + (hb >> 1) * 8 + (lane & 7)) * 80 + (hb & 1) * 16);
    #pragma unroll
    for (int ks = 0; ks < 2; ks++) {
        uint32_t a[4][4];
        #pragma unroll
        for (int mt = 0; mt < 4; mt++)
            LDSM4(a[mt], A + abase + mt * 16 * 80 + ks * 32);
        #pragma unroll
        for (int np = 0; np < 2; np++) {
            uint32_t bh4[4], bl4[4];
            LDSM4(bh4, Bh + bbase + np * 16 * 80 + ks * 32);
            LDSM4(bl4, Bl + bbase + np * 16 * 80 + ks * 32);
            #pragma unroll
            for (int mt = 0; mt < 4; mt++) {
                mma_f16(acc[mt][2*np],   a[mt], bh4[0], bh4[1]);
                mma_f16(acc[mt][2*np],   a[mt], bl4[0], bl4[1]);
                mma_f16(acc[mt][2*np+1], a[mt], bh4[2], bh4[3]);
                mma_f16(acc[mt][2*np+1], a[mt], bl4[2], bl4[3]);
            }
        }
    }
}

// ---------------------------------------------------------------------------
// 128x128 GEMM, K=1024, 2-stage cp.async, single sync per chunk.
// ---------------------------------------------------------------------------
#define PSTG 30720
#define GEMM_SMEM (2*PSTG)

__device__ __forceinline__ void gissue(uint32_t sbase,
    const __half* A, const __half* Bh, const __half* Bl, int tid)
{
    #pragma unroll 2
    for (int idx = tid; idx < 512; idx += 256) {
        int r = idx >> 2, f = idx & 3;
        uint32_t so = (uint32_t)(r * 80 + f * 16);
        size_t go = (size_t)r * 1024 + f * 8;
        cpa16(sbase + so,         A + go);
        cpa16(sbase + 10240 + so, Bh + go);
        cpa16(sbase + 20480 + so, Bl + go);
    }
}

template<typename EPI>
__device__ __forceinline__ void gemm128(
    const __half* A, const __half* Bh, const __half* Bl, int tid, EPI epi)
{
    extern __shared__ char sm[];
    const uint32_t sb = smem_u32(sm);
    const int lane = tid & 31, wid = tid >> 5;
    const int wm = wid & 1, wn = wid >> 1;   // 2 x 4 warp grid

    float acc[4][4][4];
    #pragma unroll
    for (int i = 0; i < 4; i++)
        #pragma unroll
        for (int j = 0; j < 4; j++)
            #pragma unroll
            for (int l = 0; l < 4; l++) acc[i][j][l] = 0.f;

    gissue(sb, A, Bh, Bl, tid);
    CP_COMMIT();
    for (int c = 0; c < 32; c++) {
        CP_WAIT(0);
        __syncthreads();
        if (c + 1 < 32) {
            gissue(sb + ((c + 1) & 1) * PSTG,
                   A + (c + 1) * 32, Bh + (c + 1) * 32, Bl + (c + 1) * 32, tid);
            CP_COMMIT();
        }
        uint32_t s = sb + (c & 1) * PSTG;
        chunk2(s, s + 10240, s + 20480, wm * 64, wn * 32, lane, acc);
    }
    epi(acc, wm, wn, lane);
}

// ---------------------------------------------------------------------------
// Kernel: QKV projections. grid (8, 64, 3)
// ---------------------------------------------------------------------------
__global__ void __launch_bounds__(256, 2) proj_kernel(
    const float* __restrict__ qb, const float* __restrict__ kb, const float* __restrict__ vb)
{
    const int z = blockIdx.z;
    const int tid = threadIdx.x;
    const int m0 = blockIdx.y * 128, n0 = blockIdx.x * 128;
    const __half* A  = g_x  + (size_t)z * IN_ELEMS + (size_t)m0 * 1024;
    const __half* Bh = g_wh + (size_t)z * W_ELEMS + (size_t)n0 * 1024;
    const __half* Bl = g_wl + (size_t)z * W_ELEMS + (size_t)n0 * 1024;
    const float* bias = (z == 0) ? qb : ((z == 1) ? kb : vb);

    gemm128(A, Bh, Bl, tid,
        [&](float acc[4][4][4], int wm, int wn, int lane) {
            const int g = lane >> 2, t = lane & 3;
            #pragma unroll
            for (int mt = 0; mt < 4; mt++) {
                int m = m0 + wm * 64 + mt * 16 + g;
                int bb = m >> 10, s = m & 1023;
                #pragma unroll
                for (int nt = 0; nt < 4; nt++) {
                    int n = n0 + wn * 32 + nt * 8 + t * 2;
                    int h = n >> 6, d = n & 63;
                    float2 bv = *(const float2*)(bias + n);
                    float c0 = acc[mt][nt][0] + bv.x, c1 = acc[mt][nt][1] + bv.y;
                    float c2 = acc[mt][nt][2] + bv.x, c3 = acc[mt][nt][3] + bv.y;
                    if (z == 0) {
                        size_t a0 = (((size_t)bb * Hn + h) * Sn + s) * Dn + d;
                        *(uint32_t*)(g_q + a0)          = packh2(c0, c1);
                        *(uint32_t*)(g_q + a0 + 8 * Dn) = packh2(c2, c3);
                    } else if (z == 1) {
                        size_t a0 = (((size_t)bb * Hn + h) * Sn + s) * Dn + d;
                        __half h0,l0,h1,l1,h2,l2,h3,l3;
                        split1(c0,h0,l0); split1(c1,h1,l1);
                        split1(c2,h2,l2); split1(c3,h3,l3);
                        *(uint32_t*)(g_kh + a0) = packh2(__half2float(h0), __half2float(h1));
                        *(uint32_t*)(g_kl + a0) = packh2(__half2float(l0), __half2float(l1));
                        *(uint32_t*)(g_kh + a0 + 8 * Dn) = packh2(__half2float(h2), __half2float(h3));
                        *(uint32_t*)(g_kl + a0 + 8 * Dn) = packh2(__half2float(l2), __half2float(l3));
                    } else {
                        // V transposed: (b,h,d,s)
                        size_t a0 = (((size_t)bb * Hn + h) * Dn + d) * Sn + s;
                        __half h0,l0,h1,l1,h2,l2,h3,l3;
                        split1(c0,h0,l0); split1(c1,h1,l1);
                        split1(c2,h2,l2); split1(c3,h3,l3);
                        g_vth[a0] = h0;          g_vtl[a0] = l0;
                        g_vth[a0 + Sn] = h1;     g_vtl[a0 + Sn] = l1;
                        g_vth[a0 + 8] = h2;      g_vtl[a0 + 8] = l2;
                        g_vth[a0 + Sn + 8] = h3; g_vtl[a0 + Sn + 8] = l3;
                    }
                }
            }
        });
}

// ---------------------------------------------------------------------------
// Pass 1: softmax row sums via single-term fp16 scores (Q single x K hi).
// Per-entry exp rel-errors (~3e-4, random sign) average to ~1e-5 in the sum.
// grid (8, 128). smem: Q@0 (18432) | KH stage st @ 18432+st*9216 | sums@36864
// ---------------------------------------------------------------------------
#define SQ 0
#define SKH(st) (18432 + (st)*9216)
#define SSUM 36864
#define SUM_SMEM 37376

__global__ void __launch_bounds__(256, 2) sum_kernel()
{
    extern __shared__ char sm[];
    const uint32_t sb = smem_u32(sm);
    float* sums = (float*)(sm + SSUM);

    const int tid = threadIdx.x, lane = tid & 31, w = tid >> 5;
    const int g = lane >> 2, t = lane & 3;
    const int wr = w * 16;
    const int hb = (lane >> 3) & 3;
    const int m0 = blockIdx.x * 128;
    const int bh = blockIdx.y;

    const __half* Qg  = g_q  + ((size_t)bh * Sn + m0) * Dn;
    const __half* Khg = g_kh + (size_t)bh * Sn * Dn;

    auto issueK = [&](int c, int st) {
        uint32_t base = sb + SKH(st);
        #pragma unroll
        for (int j = 0; j < 2; j++) {
            int idx = tid + j * 256;
            int r = idx >> 3, f = idx & 7;
            cpa16(base + r * 144 + f * 16, Khg + (size_t)(c * 64 + r) * Dn + f * 8);
        }
    };

    #pragma unroll
    for (int j = 0; j < 4; j++) {
        int idx = tid + j * 256;
        int r = idx >> 3, f = idx & 7;
        cpa16(sb + SQ + r * 144 + f * 16, Qg + (size_t)r * Dn + f * 8);
    }
    issueK(0, 0);
    CP_COMMIT();

    float rs0 = 0.f, rs1 = 0.f;
    for (int c = 0; c < 16; c++) {
        CP_WAIT(0);
        __syncthreads();
        if (c + 1 < 16) { issueK(c + 1, (c + 1) & 1); CP_COMMIT(); }
        const uint32_t stg = sb + SKH(c & 1);

        float sa[8][4];
        #pragma unroll
        for (int i = 0; i < 8; i++)
            #pragma unroll
            for (int l = 0; l < 4; l++) sa[i][l] = 0.f;
        #pragma unroll
        for (int ks = 0; ks < 4; ks++) {
            uint32_t qa[4];
            LDSM4(qa, sb + SQ + (wr + (lane & 15)) * 144 + (lane >> 4) * 16 + ks * 32);
            #pragma unroll
            for (int np = 0; np < 4; np++) {
                uint32_t bo = (uint32_t)((np * 16 + (hb >> 1) * 8 + (lane & 7)) * 144
                                         + (hb & 1) * 16 + ks * 32);
                uint32_t kh4[4];
                LDSM4(kh4, stg + bo);
                mma_f16(sa[2*np],   qa, kh4[0], kh4[1]);
                mma_f16(sa[2*np+1], qa, kh4[2], kh4[3]);
            }
        }
        #pragma unroll
        for (int j = 0; j < 8; j++) {
            rs0 += __expf(sa[j][0] * 0.125f) + __expf(sa[j][1] * 0.125f);
            rs1 += __expf(sa[j][2] * 0.125f) + __expf(sa[j][3] * 0.125f);
        }
    }

    rs0 += __shfl_xor_sync(0xffffffffu, rs0, 1);
    rs0 += __shfl_xor_sync(0xffffffffu, rs0, 2);
    rs1 += __shfl_xor_sync(0xffffffffu, rs1, 1);
    rs1 += __shfl_xor_sync(0xffffffffu, rs1, 2);
    if (t == 0) { sums[wr + g] = rs0; sums[wr + g + 8] = rs1; }
    __syncthreads();
    if (tid < 128)
        g_inv[((size_t)bh << 10) + m0 + tid] = 1.0f / sums[tid];
}

// ---------------------------------------------------------------------------
// Pass 2: fused attention, writes NORMALIZED attn directly + PV -> ctx.
// grid (8, 128). smem layout unchanged from R8 fused.
// ---------------------------------------------------------------------------
#define FQ 0
#define FST(st) (18432 + (st)*36864)
#define FSUM 92160
#define FUSED_SMEM 92672

__global__ void __launch_bounds__(256, 2) fused_attn_kernel(float* __restrict__ attn)
{
    extern __shared__ char sm[];
    const uint32_t sb = smem_u32(sm);
    float* sums = (float*)(sm + FSUM);

    const int tid = threadIdx.x, lane = tid & 31, w = tid >> 5;
    const int g = lane >> 2, t = lane & 3;
    const int wr = w * 16;
    const int hb = (lane >> 3) & 3;
    const int m0 = blockIdx.x * 128;
    const int bh = blockIdx.y;

    const __half* Qg  = g_q   + ((size_t)bh * Sn + m0) * Dn;
    const __half* Khg = g_kh  + (size_t)bh * Sn * Dn;
    const __half* Klg = g_kl  + (size_t)bh * Sn * Dn;
    const __half* Vhg = g_vth + (size_t)bh * Dn * Sn;
    const __half* Vlg = g_vtl + (size_t)bh * Dn * Sn;
    float* attnB = attn + ((size_t)bh * Sn + m0) * Sn;

    if (tid < 128) sums[tid] = g_inv[((size_t)bh << 10) + m0 + tid];

    auto issueKV = [&](int c, int st) {
        uint32_t base = sb + FST(st);
        #pragma unroll
        for (int j = 0; j < 2; j++) {
            int idx = tid + j * 256;
            int r = idx >> 3, f = idx & 7;
            size_t go = (size_t)(c * 64 + r) * Dn + f * 8;
            cpa16(base + r * 144 + f * 16,        Khg + go);
            cpa16(base + 9216 + r * 144 + f * 16, Klg + go);
        }
        #pragma unroll
        for (int j = 0; j < 2; j++) {
            int idx = tid + j * 256;
            int d = idx >> 3, f = idx & 7;
            size_t go = (size_t)d * Sn + c * 64 + f * 8;
            cpa16(base + 18432 + d * 144 + f * 16, Vhg + go);
            cpa16(base + 27648 + d * 144 + f * 16, Vlg + go);
        }
    };

    #pragma unroll
    for (int j = 0; j < 4; j++) {
        int idx = tid + j * 256;
        int r = idx >> 3, f = idx & 7;
        cpa16(sb + FQ + r * 144 + f * 16, Qg + (size_t)r * Dn + f * 8);
    }
    issueKV(0, 0);
    CP_COMMIT();

    __syncthreads();                    // sums visible
    const float iv0 = sums[wr + g], iv1 = sums[wr + g + 8];

    float O[8][4];
    #pragma unroll
    for (int i = 0; i < 8; i++)
        #pragma unroll
        for (int l = 0; l < 4; l++) O[i][l] = 0.f;

    for (int c = 0; c < 16; c++) {
        CP_WAIT(0);
        __syncthreads();
        if (c + 1 < 16) { issueKV(c + 1, (c + 1) & 1); CP_COMMIT(); }
        const uint32_t stg = sb + FST(c & 1);

        // ---- S = Q K^T (M16 x N64keys x K64d), 2-term on K ----
        float sa[8][4];
        #pragma unroll
        for (int i = 0; i < 8; i++)
            #pragma unroll
            for (int l = 0; l < 4; l++) sa[i][l] = 0.f;
        #pragma unroll
        for (int ks = 0; ks < 4; ks++) {
            uint32_t qa[4];
            LDSM4(qa, sb + FQ + (wr + (lane & 15)) * 144 + (lane >> 4) * 16 + ks * 32);
            #pragma unroll
            for (int np = 0; np < 4; np++) {
                uint32_t bo = (uint32_t)((np * 16 + (hb >> 1) * 8 + (lane & 7)) * 144
                                         + (hb & 1) * 16 + ks * 32);
                uint32_t kh4[4], kl4[4];
                LDSM4(kh4, stg + bo);
                LDSM4(kl4, stg + 9216 + bo);
                mma_f16(sa[2*np],   qa, kh4[0], kh4[1]);
                mma_f16(sa[2*np],   qa, kl4[0], kl4[1]);
                mma_f16(sa[2*np+1], qa, kh4[2], kh4[3]);
                mma_f16(sa[2*np+1], qa, kl4[2], kl4[3]);
            }
        }
        // ---- normalized exp, final attn write ----
        const int cb = c * 64;
        #pragma unroll
        for (int j = 0; j < 8; j++) {
            float e0 = __expf(sa[j][0] * 0.125f) * iv0;
            float e1 = __expf(sa[j][1] * 0.125f) * iv0;
            float e2 = __expf(sa[j][2] * 0.125f) * iv1;
            float e3 = __expf(sa[j][3] * 0.125f) * iv1;
            *(float2*)(attnB + (size_t)(wr + g) * Sn + cb + j * 8 + t * 2)     = make_float2(e0, e1);
            *(float2*)(attnB + (size_t)(wr + g + 8) * Sn + cb + j * 8 + t * 2) = make_float2(e2, e3);
            sa[j][0] = e0; sa[j][1] = e1; sa[j][2] = e2; sa[j][3] = e3;
        }
        // ---- repack normalized P -> PV A-frags ----
        uint32_t PA[4][4];
        #pragma unroll
        for (int i = 0; i < 4; i++) {
            PA[i][0] = packh2(sa[2*i][0],   sa[2*i][1]);
            PA[i][1] = packh2(sa[2*i][2],   sa[2*i][3]);
            PA[i][2] = packh2(sa[2*i+1][0], sa[2*i+1][1]);
            PA[i][3] = packh2(sa[2*i+1][2], sa[2*i+1][3]);
        }
        // ---- O += P V (M16 x N64d x K64keys), 2-term on V ----
        #pragma unroll
        for (int ks = 0; ks < 4; ks++) {
            #pragma unroll
            for (int np = 0; np < 4; np++) {
                uint32_t bo = (uint32_t)((np * 16 + (hb >> 1) * 8 + (lane & 7)) * 144
                                         + (hb & 1) * 16 + ks * 32);
                uint32_t vh4[4], vl4[4];
                LDSM4(vh4, stg + 18432 + bo);
                LDSM4(vl4, stg + 27648 + bo);
                mma_f16(O[2*np],   PA[ks], vh4[0], vh4[1]);
                mma_f16(O[2*np],   PA[ks], vl4[0], vl4[1]);
                mma_f16(O[2*np+1], PA[ks], vh4[2], vh4[3]);
                mma_f16(O[2*np+1], PA[ks], vl4[2], vl4[3]);
            }
        }
    }

    // ---- O epilogue: write ctx fp16 (already normalized) ----
    {
        int m = m0 + wr + g;
        int bb = bh >> 4, h = bh & 15;
        __half* cbase0 = g_ctx + ((size_t)(bb * Sn + m)) * En + h * Dn;
        __half* cbase1 = g_ctx + ((size_t)(bb * Sn + m + 8)) * En + h * Dn;
        #pragma unroll
        for (int nt = 0; nt < 8; nt++) {
            int d = nt * 8 + t * 2;
            *(uint32_t*)(cbase0 + d) = packh2(O[nt][0], O[nt][1]);
            *(uint32_t*)(cbase1 + d) = packh2(O[nt][2], O[nt][3]);
        }
    }
}

// ---------------------------------------------------------------------------
// Kernel: output projection. grid (8, 64)
// ---------------------------------------------------------------------------
__global__ void __launch_bounds__(256, 2) outproj_kernel(
    const float* __restrict__ ob, float* __restrict__ Out)
{
    const int tid = threadIdx.x;
    const int m0 = blockIdx.y * 128, n0 = blockIdx.x * 128;
    const __half* A  = g_ctx + (size_t)m0 * 1024;
    const __half* Bh = g_wh + (size_t)3 * W_ELEMS + (size_t)n0 * 1024;
    const __half* Bl = g_wl + (size_t)3 * W_ELEMS + (size_t)n0 * 1024;

    gemm128(A, Bh, Bl, tid,
        [&](float acc[4][4][4], int wm, int wn, int lane) {
            const int g = lane >> 2, t = lane & 3;
            #pragma unroll
            for (int mt = 0; mt < 4; mt++) {
                int m = m0 + wm * 64 + mt * 16 + g;
                float* orow = Out + (size_t)m * En;
                #pragma unroll
                for (int nt = 0; nt < 4; nt++) {
                    int n = n0 + wn * 32 + nt * 8 + t * 2;
                    float2 bv = *(const float2*)(ob + n);
                    *(float2*)(orow + n) =
                        make_float2(acc[mt][nt][0] + bv.x, acc[mt][nt][1] + bv.y);
                    *(float2*)(orow + 8 * En + n) =
                        make_float2(acc[mt][nt][2] + bv.x, acc[mt][nt][3] + bv.y);
                }
            }
        });
}

// ---------------------------------------------------------------------------
extern "C" void kernel_launch(void* const* d_in, const int* in_sizes, int n_in,
                              void* d_out, int out_size)
{
    const float* q_in  = (const float*)d_in[0];
    const float* k_in  = (const float*)d_in[1];
    const float* v_in  = (const float*)d_in[2];
    const float* q_w   = (const float*)d_in[3];
    const float* q_b   = (const float*)d_in[4];
    const float* k_w   = (const float*)d_in[5];
    const float* k_b   = (const float*)d_in[6];
    const float* v_w   = (const float*)d_in[7];
    const float* v_b   = (const float*)d_in[8];
    const float* out_w = (const float*)d_in[9];
    const float* out_b = (const float*)d_in[10];

    float* out  = (float*)d_out;
    float* attn = out;                  // (B,H,S,S)
    float* outp = out + ATTN_ELEMS;     // (B,S,E)

    cudaFuncSetAttribute(proj_kernel,       cudaFuncAttributeMaxDynamicSharedMemorySize, GEMM_SMEM);
    cudaFuncSetAttribute(sum_kernel,        cudaFuncAttributeMaxDynamicSharedMemorySize, SUM_SMEM);
    cudaFuncSetAttribute(fused_attn_kernel, cudaFuncAttributeMaxDynamicSharedMemorySize, FUSED_SMEM);
    cudaFuncSetAttribute(outproj_kernel,    cudaFuncAttributeMaxDynamicSharedMemorySize, GEMM_SMEM);

    split_kernel<<<dim3(8192, 7), 256>>>(q_in, k_in, v_in, q_w, k_w, v_w, out_w);
    proj_kernel<<<dim3(8, 64, 3), 256, GEMM_SMEM>>>(q_b, k_b, v_b);
    sum_kernel<<<dim3(8, 128), 256, SUM_SMEM>>>();
    fused_attn_kernel<<<dim3(8, 128), 256, FUSED_SMEM>>>(attn);
    outproj_kernel<<<dim3(8, 64), 256, GEMM_SMEM>>>(out_b, outp);
}